// round 12
// baseline (speedup 1.0000x reference)
#include <cuda_runtime.h>
#include <math.h>
#include <stdint.h>

#define NN 100000
#define EE 1600000
#define FF 64
#define HH 128
#define GG 256
#define EPB 128
#define ETHREADS 256

// smem float offsets (edge kernel: h tile + biases only; weights live in L1/L2)
#define SMF_H 0          // h [128][128] swizzled = 16384 floats
#define SMF_B2 16384     // 128
#define SMF_B3 16512     // 64
#define EDGE_SMEM (16576 * 4)   // 66304 B -> 2 CTAs/SM

// scratch (static __device__ arrays: the sanctioned no-alloc workaround)
__device__ float g_Apre[(size_t)NN*HH];
__device__ float g_Bpre[(size_t)NN*HH];
__device__ float g_x1[(size_t)NN*FF];
__device__ float g_x2[(size_t)NN*FF];
// pair-packed tf32 weights: wp2 = [128 rows][64 float2] at 0, wp3 = [64 rows][64 float2] at 16384
__device__ float g_wimg[24576];

__device__ __forceinline__ float silu_f(float v) {
    return __fdividef(v, 1.0f + __expf(-v));
}
// 1-MUFU silu via tanh.approx (err ~2^-10.7, below tf32 rounding of consumers)
__device__ __forceinline__ float silu_t(float v) {
    float t;
    asm("tanh.approx.f32 %0, %1;" : "=f"(t) : "f"(0.5f * v));
    return 0.5f * v * (1.0f + t);
}
__device__ __forceinline__ float to_tf32(float x) {
    float r; asm("cvt.rna.tf32.f32 %0, %1;" : "=f"(r) : "f"(x)); return r;
}
__device__ __forceinline__ void mma8(float* d, const unsigned* a, unsigned b0, unsigned b1) {
    asm volatile("mma.sync.aligned.m16n8k8.row.col.f32.tf32.tf32.f32 "
        "{%0,%1,%2,%3}, {%4,%5,%6,%7}, {%8,%9}, {%0,%1,%2,%3};"
        : "+f"(d[0]), "+f"(d[1]), "+f"(d[2]), "+f"(d[3])
        : "r"(a[0]), "r"(a[1]), "r"(a[2]), "r"(a[3]), "r"(b0), "r"(b1));
}
// packed f32x2 helpers (for precomp)
__device__ __forceinline__ void fma2(unsigned long long& d, unsigned long long a, unsigned long long b) {
    asm("fma.rn.f32x2 %0, %1, %2, %0;" : "+l"(d) : "l"(a), "l"(b));
}
__device__ __forceinline__ unsigned long long bcast2(float a) {
    unsigned long long r; asm("mov.b64 %0, {%1, %1};" : "=l"(r) : "f"(a)); return r;
}
__device__ __forceinline__ float2 unpk(unsigned long long v) {
    float2 r; asm("mov.b64 {%0, %1}, %2;" : "=f"(r.x), "=f"(r.y) : "l"(v)); return r;
}

// ---------------------------------------------------------------------------
// Combined precompute:
//   part 0: Apre = x @ W1[0:64] + b1
//   part 1: Bpre = x[:,3:] @ W1[64:125]
//   part 2 (blocks 0..47): pair-packed tf32 weight image
//     wp2[n*64 + ks*4 + tig] = (W2[k][n], W2[k+4][n]), k = ks*8+tig
//     wp3[m*64 + ks*4 + tig] = (W3[k][m], W3[k+4][m])
// ---------------------------------------------------------------------------
__global__ void __launch_bounds__(256) precomp_kernel(
    const float* __restrict__ xin, const float* __restrict__ W1l, const float* __restrict__ b1l,
    const float* __restrict__ W2l, const float* __restrict__ W3l,
    float* __restrict__ Apre, float* __restrict__ Bpre, float* __restrict__ wimg)
{
    int part = blockIdx.y;
    int tid = threadIdx.x;

    if (part == 2) {
        int idx = blockIdx.x * 256 + tid;
        if (idx < 8192) {
            int n = idx >> 6, j = idx & 63;
            int k = (j >> 2) * 8 + (j & 3);
            float2 v = make_float2(to_tf32(W2l[k*128 + n]), to_tf32(W2l[(k+4)*128 + n]));
            *(float2*)(wimg + idx*2) = v;
        } else if (idx < 12288) {
            int i2 = idx - 8192;
            int n = i2 >> 6, j = i2 & 63;
            int k = (j >> 2) * 8 + (j & 3);
            float2 v = make_float2(to_tf32(W3l[k*64 + n]), to_tf32(W3l[(k+4)*64 + n]));
            *(float2*)(wimg + 16384 + i2*2) = v;
        }
        return;
    }

    __shared__ float xs[32*64];
    size_t nb = (size_t)blockIdx.x * 32;

    const float4* xg = (const float4*)(xin + nb*64);
    float4* xs4 = (float4*)xs;
#pragma unroll
    for (int i = 0; i < 2; ++i) xs4[tid + i*256] = xg[tid + i*256];
    __syncthreads();

    int tx = tid & 31, ty = tid >> 5;
    unsigned long long acc[4][2];
#pragma unroll
    for (int a = 0; a < 4; ++a) { acc[a][0] = 0ull; acc[a][1] = 0ull; }

    int cbeg = part ? 3 : 0;
    const float* Wb = part ? (W1l + 61*128) : W1l;
#pragma unroll 4
    for (int c = cbeg; c < 64; ++c) {
        ulonglong2 wv = *(const ulonglong2*)(Wb + c*128 + tx*4);
#pragma unroll
        for (int ni = 0; ni < 4; ++ni) {
            unsigned long long av = bcast2(xs[(ty*4+ni)*64 + c]);
            fma2(acc[ni][0], av, wv.x);
            fma2(acc[ni][1], av, wv.y);
        }
    }

    float4 bv = make_float4(0.f,0.f,0.f,0.f);
    float* outp;
    if (part) outp = Bpre;
    else { outp = Apre; bv = *(const float4*)(b1l + tx*4); }
#pragma unroll
    for (int ni = 0; ni < 4; ++ni) {
        float2 p0 = unpk(acc[ni][0]), p1 = unpk(acc[ni][1]);
        float4 r = make_float4(p0.x+bv.x, p0.y+bv.y, p1.x+bv.z, p1.y+bv.w);
        *(float4*)(outp + (nb + ty*4 + ni)*128 + tx*4) = r;
    }
}

// ---------------------------------------------------------------------------
// Fused edge kernel: gather h1 (tf32) -> tf32 MMA (h1@W2) -> silu -> tf32 MMA
// (h2@W3) -> silu -> atomic scatter. 128 edges/block, 8 warps, 2 CTAs/SM.
// A from XOR-swizzled smem; B via LDG.64 from pair-packed global image (L1/L2-hot).
// ---------------------------------------------------------------------------
__global__ void __launch_bounds__(ETHREADS, 2) edge_kernel(
    const float* __restrict__ Apre, const float* __restrict__ Bpre, const float* __restrict__ xin,
    const int* __restrict__ srcp, const int* __restrict__ dstp,
    const float* __restrict__ wdrow, const float* __restrict__ wimg, const float* __restrict__ b2l,
    const float* __restrict__ b3l, float* __restrict__ xout)
{
    extern __shared__ float sm[];
    float* hs  = sm + SMF_H;
    float* b2s = sm + SMF_B2;
    float* b3s = sm + SMF_B3;

    const int tid = threadIdx.x;
    const int w = tid >> 5, lane = tid & 31;
    const int g = lane >> 2, tig = lane & 3;
    const int eb = blockIdx.x * EPB;
    const float2* wp2 = (const float2*)wimg;            // [128][64]
    const float2* wp3 = (const float2*)(wimg + 16384);  // [64][64]

    // stage biases (tiny)
    if (tid < 128) b2s[tid] = b2l[tid];
    else if (tid < 192) b3s[tid-128] = b3l[tid-128];

    // gather h1: warp covers 16 edges, lane covers k-chunk lane*4..lane*4+3
    {
        float4 wd4 = __ldg((const float4*)(wdrow + lane*4));
        int ids = (lane < 16) ? __ldg(srcp + eb + w*16 + lane)
                              : __ldg(dstp + eb + w*16 + (lane - 16));
#pragma unroll 4
        for (int it = 0; it < 16; ++it) {
            int s = __shfl_sync(0xffffffffu, ids, it);
            int d = __shfl_sync(0xffffffffu, ids, 16 + it);
            float4 xs4 = __ldg((const float4*)(xin + (size_t)s*64));
            float4 xd4 = __ldg((const float4*)(xin + (size_t)d*64));
            float dx = xs4.x - xd4.x, dy = xs4.y - xd4.y, dz = xs4.z - xd4.z;
            float dist2 = dx*dx + dy*dy + dz*dz;
            float4 a = __ldg((const float4*)(Apre + (size_t)d*128 + lane*4));
            float4 b = __ldg((const float4*)(Bpre + (size_t)s*128 + lane*4));
            float4 v;
            v.x = to_tf32(silu_t(a.x + b.x + dist2*wd4.x));
            v.y = to_tf32(silu_t(a.y + b.y + dist2*wd4.y));
            v.z = to_tf32(silu_t(a.z + b.z + dist2*wd4.z));
            v.w = to_tf32(silu_t(a.w + b.w + dist2*wd4.w));
            int e = w*16 + it;
            int word = e*128 + ((lane*4) ^ ((e & 7) << 2));
            *(float4*)(hs + word) = v;
        }
    }
    __syncthreads();

    const int e0 = (w & 3) * 32;
    const int n0 = (w >> 2) * 64;
    const int xm = g << 2;
    const float* hA0 = hs + (e0 + g) * 128;
    const float* hA1 = hs + (e0 + g + 8) * 128;
    const float* hA2 = hs + (e0 + g + 16) * 128;
    const float* hA3 = hs + (e0 + g + 24) * 128;

    // ---- GEMM2: [128e x 128] = h1 @ W2 ----
    float acc[2][8][4];
#pragma unroll
    for (int mf = 0; mf < 2; ++mf)
#pragma unroll
        for (int nf = 0; nf < 8; ++nf)
#pragma unroll
            for (int q = 0; q < 4; ++q) acc[mf][nf][q] = 0.f;

#pragma unroll
    for (int ks = 0; ks < 16; ++ks) {
        int off1 = (ks*8 + tig) ^ xm;
        int off2 = (ks*8 + tig + 4) ^ xm;
        unsigned a[2][4];
        a[0][0] = __float_as_uint(hA0[off1]);
        a[0][1] = __float_as_uint(hA1[off1]);
        a[0][2] = __float_as_uint(hA0[off2]);
        a[0][3] = __float_as_uint(hA1[off2]);
        a[1][0] = __float_as_uint(hA2[off1]);
        a[1][1] = __float_as_uint(hA3[off1]);
        a[1][2] = __float_as_uint(hA2[off2]);
        a[1][3] = __float_as_uint(hA3[off2]);
        int bcol = ks*4 + tig;
#pragma unroll
        for (int nf = 0; nf < 8; ++nf) {
            int n = n0 + nf*8 + g;
            float2 wv = __ldg(wp2 + n*64 + bcol);
            unsigned b0 = __float_as_uint(wv.x);
            unsigned b1 = __float_as_uint(wv.y);
            mma8(acc[0][nf], a[0], b0, b1);
            mma8(acc[1][nf], a[1], b0, b1);
        }
    }
    __syncthreads();   // all h1 reads complete before h2 overwrites

    // ---- epilogue1: h2 = tf32(silu(D2 + b2)) back into hs ----
#pragma unroll
    for (int mf = 0; mf < 2; ++mf) {
        int elo = e0 + mf*16 + g;
        float* hlo = hs + elo*128;
        float* hhi = hs + (elo + 8)*128;
#pragma unroll
        for (int nf = 0; nf < 8; ++nf) {
            int n = n0 + nf*8 + 2*tig;
            float bb0 = b2s[n], bb1 = b2s[n+1];
            float2 vlo, vhi;
            vlo.x = to_tf32(silu_t(acc[mf][nf][0] + bb0));
            vlo.y = to_tf32(silu_t(acc[mf][nf][1] + bb1));
            vhi.x = to_tf32(silu_t(acc[mf][nf][2] + bb0));
            vhi.y = to_tf32(silu_t(acc[mf][nf][3] + bb1));
            int woff = n ^ xm;
            *(float2*)(hlo + woff) = vlo;
            *(float2*)(hhi + woff) = vhi;
        }
    }
    __syncthreads();

    // ---- GEMM3: [128e x 64] = h2 @ W3 ----
    const int n03 = (w >> 2) * 32;
    float acc3[2][4][4];
#pragma unroll
    for (int mf = 0; mf < 2; ++mf)
#pragma unroll
        for (int nf = 0; nf < 4; ++nf)
#pragma unroll
            for (int q = 0; q < 4; ++q) acc3[mf][nf][q] = 0.f;

#pragma unroll
    for (int ks = 0; ks < 16; ++ks) {
        int off1 = (ks*8 + tig) ^ xm;
        int off2 = (ks*8 + tig + 4) ^ xm;
        unsigned a[2][4];
        a[0][0] = __float_as_uint(hA0[off1]);
        a[0][1] = __float_as_uint(hA1[off1]);
        a[0][2] = __float_as_uint(hA0[off2]);
        a[0][3] = __float_as_uint(hA1[off2]);
        a[1][0] = __float_as_uint(hA2[off1]);
        a[1][1] = __float_as_uint(hA3[off1]);
        a[1][2] = __float_as_uint(hA2[off2]);
        a[1][3] = __float_as_uint(hA3[off2]);
        int bcol = ks*4 + tig;
#pragma unroll
        for (int nf = 0; nf < 4; ++nf) {
            int n = n03 + nf*8 + g;
            float2 wv = __ldg(wp3 + n*64 + bcol);
            unsigned b0 = __float_as_uint(wv.x);
            unsigned b1 = __float_as_uint(wv.y);
            mma8(acc3[0][nf], a[0], b0, b1);
            mma8(acc3[1][nf], a[1], b0, b1);
        }
    }

    // ---- epilogue2: silu(D3 + b3), scalar atomic scatter-add ----
#pragma unroll
    for (int mf = 0; mf < 2; ++mf) {
        int elo = e0 + mf*16 + g;
        int dlo = __ldg(dstp + eb + elo);
        int dhi = __ldg(dstp + eb + elo + 8);
        float* olo = xout + (size_t)dlo*64;
        float* ohi = xout + (size_t)dhi*64;
#pragma unroll
        for (int nf = 0; nf < 4; ++nf) {
            int n = n03 + nf*8 + 2*tig;
            float bb0 = b3s[n], bb1 = b3s[n+1];
            atomicAdd(olo + n,     silu_f(acc3[mf][nf][0] + bb0));
            atomicAdd(olo + n + 1, silu_f(acc3[mf][nf][1] + bb1));
            atomicAdd(ohi + n,     silu_f(acc3[mf][nf][2] + bb0));
            atomicAdd(ohi + n + 1, silu_f(acc3[mf][nf][3] + bb1));
        }
    }
}

// ---------------------------------------------------------------------------
// Pooling + readout MLP (unchanged)
// ---------------------------------------------------------------------------
__global__ void __launch_bounds__(64) pool_head_kernel(
    const float* __restrict__ xf, const int* __restrict__ batch, const float* __restrict__ u,
    const float* __restrict__ LW1, const float* __restrict__ Lb1,
    const float* __restrict__ LW2, const float* __restrict__ Lb2,
    const float* __restrict__ LW3, const float* __restrict__ Lb3,
    float* __restrict__ out)
{
    __shared__ float pooled[194];
    __shared__ float hbuf[64];
    int g = blockIdx.x, f = threadIdx.x;

    int start, end;
    {
        int lo = 0, hi = NN;
        while (lo < hi) { int m = (lo+hi) >> 1; if (batch[m] < g) lo = m+1; else hi = m; }
        start = lo;
        hi = NN;
        while (lo < hi) { int m = (lo+hi) >> 1; if (batch[m] < g+1) lo = m+1; else hi = m; }
        end = lo;
    }

    float s = 0.f, mx = -3.402823466e38f;
    for (int n = start; n < end; ++n) {
        float v = xf[(size_t)n*64 + f];
        s += v; mx = fmaxf(mx, v);
    }
    float cnt = fmaxf((float)(end - start), 1.f);
    pooled[f]      = s;
    pooled[64+f]   = s / cnt;
    pooled[128+f]  = mx;
    if (f < 2) pooled[192+f] = u[g*2+f];
    __syncthreads();

    float a = Lb1[f];
    for (int c = 0; c < 194; ++c) a += pooled[c] * LW1[c*64+f];
    float h = silu_f(a);
    hbuf[f] = h;
    __syncthreads();

    a = Lb2[f];
    for (int c = 0; c < 64; ++c) a += hbuf[c] * LW2[c*64+f];
    h = silu_f(a);
    __syncthreads();
    hbuf[f] = h;
    __syncthreads();

    if (f < 2) {
        a = Lb3[f];
        for (int c = 0; c < 64; ++c) a += hbuf[c] * LW3[c*2+f];
        out[g*2+f] = a;
    }
}

// ---------------------------------------------------------------------------
extern "C" void kernel_launch(void* const* d_in, const int* in_sizes, int n_in,
                              void* d_out, int out_size) {
    const float* x    = (const float*)d_in[0];
    const float* u    = (const float*)d_in[1];
    const int*   ei   = (const int*)d_in[2];
    const int*   batch= (const int*)d_in[3];
    const float* W1   = (const float*)d_in[4];
    const float* b1   = (const float*)d_in[5];
    const float* W2   = (const float*)d_in[6];
    const float* b2   = (const float*)d_in[7];
    const float* W3   = (const float*)d_in[8];
    const float* b3   = (const float*)d_in[9];
    const float* LW1  = (const float*)d_in[10];
    const float* Lb1  = (const float*)d_in[11];
    const float* LW2  = (const float*)d_in[12];
    const float* Lb2  = (const float*)d_in[13];
    const float* LW3  = (const float*)d_in[14];
    const float* Lb3  = (const float*)d_in[15];
    float* out = (float*)d_out;

    float *Apre, *Bpre, *x1, *x2, *wimg;
    cudaGetSymbolAddress((void**)&Apre, g_Apre);
    cudaGetSymbolAddress((void**)&Bpre, g_Bpre);
    cudaGetSymbolAddress((void**)&x1,   g_x1);
    cudaGetSymbolAddress((void**)&x2,   g_x2);
    cudaGetSymbolAddress((void**)&wimg, g_wimg);

    cudaFuncSetAttribute(edge_kernel, cudaFuncAttributeMaxDynamicSharedMemorySize, EDGE_SMEM);

    const int* srcp = ei;
    const int* dstp = ei + EE;

    // zero both layer outputs up front (also puts edge_kernel at launch #6 for ncu)
    cudaMemsetAsync(x1, 0, (size_t)NN*FF*sizeof(float));
    cudaMemsetAsync(x2, 0, (size_t)NN*FF*sizeof(float));

    for (int l = 0; l < 2; ++l) {
        const float* xin = l ? (const float*)x1 : x;
        float* xout = l ? x2 : x1;
        precomp_kernel<<<dim3(3125, 3, 1), 256>>>(
            xin, W1 + (size_t)l*126*128, b1 + (size_t)l*128,
            W2 + (size_t)l*128*128, W3 + (size_t)l*128*64,
            Apre, Bpre, wimg);
        edge_kernel<<<EE/EPB, ETHREADS, EDGE_SMEM>>>(
            Apre, Bpre, xin, srcp, dstp,
            W1 + (size_t)l*126*128 + 125*128,
            wimg, b2 + (size_t)l*128,
            b3 + (size_t)l*64, xout);
    }
    pool_head_kernel<<<GG, 64>>>(x2, batch, u, LW1, Lb1, LW2, Lb2, LW3, Lb3, out);
}

// round 13
// speedup vs baseline: 1.4039x; 1.4039x over previous
#include <cuda_runtime.h>
#include <cuda_fp16.h>
#include <math.h>
#include <stdint.h>

#define NN 100000
#define EE 1600000
#define FF 64
#define HH 128
#define GG 256
#define EPB 128
#define ETHREADS 256

// smem layout (words = 32-bit): h tile 128 rows x 64 half2-words, then biases
#define SMW_H 0
#define SMW_B2 8192
#define SMW_B3 8320
#define EDGE_SMEM ((8384) * 4)   // 33536 B -> 2 CTAs/SM (reg-limited)

// scratch (static __device__ arrays: the sanctioned no-alloc workaround)
__device__ float g_Apre[(size_t)NN*HH];
__device__ float g_Bpre[(size_t)NN*HH];
__device__ float g_x1[(size_t)NN*FF];
__device__ float g_x2[(size_t)NN*FF];
// fp16 packed weight image:
//   wq2: [128 n][32] uint2, entry (n, ks*4+tig) = halves (W2[k][n],W2[k+1][n],W2[k+8][n],W2[k+9][n]), k=ks*16+tig*2
//   wq3: [64 n][32] uint2 at offset 4096
__device__ uint2 g_wimg[6144];

__device__ __forceinline__ float silu_f(float v) {
    return __fdividef(v, 1.0f + __expf(-v));
}
// 1-MUFU silu via tanh.approx (err ~2^-10.7, at the level of fp16 rounding of consumers)
__device__ __forceinline__ float silu_t(float v) {
    float t;
    asm("tanh.approx.f32 %0, %1;" : "=f"(t) : "f"(0.5f * v));
    return 0.5f * v * (1.0f + t);
}
__device__ __forceinline__ unsigned pk_h2(float a, float b) {
    __half2 h = __floats2half2_rn(a, b);
    return *reinterpret_cast<unsigned*>(&h);
}
// m16n8k16 fp16 MMA, fp32 accumulate
__device__ __forceinline__ void mma16(float* d, const unsigned* a, unsigned b0, unsigned b1) {
    asm volatile("mma.sync.aligned.m16n8k16.row.col.f32.f16.f16.f32 "
        "{%0,%1,%2,%3}, {%4,%5,%6,%7}, {%8,%9}, {%0,%1,%2,%3};"
        : "+f"(d[0]), "+f"(d[1]), "+f"(d[2]), "+f"(d[3])
        : "r"(a[0]), "r"(a[1]), "r"(a[2]), "r"(a[3]), "r"(b0), "r"(b1));
}
// packed f32x2 helpers (for precomp)
__device__ __forceinline__ void fma2(unsigned long long& d, unsigned long long a, unsigned long long b) {
    asm("fma.rn.f32x2 %0, %1, %2, %0;" : "+l"(d) : "l"(a), "l"(b));
}
__device__ __forceinline__ unsigned long long bcast2(float a) {
    unsigned long long r; asm("mov.b64 %0, {%1, %1};" : "=l"(r) : "f"(a)); return r;
}
__device__ __forceinline__ float2 unpk(unsigned long long v) {
    float2 r; asm("mov.b64 {%0, %1}, %2;" : "=f"(r.x), "=f"(r.y) : "l"(v)); return r;
}

// ---------------------------------------------------------------------------
// Combined precompute:
//   part 0: Apre = x @ W1[0:64] + b1
//   part 1: Bpre = x[:,3:] @ W1[64:125]
//   part 2: fp16 packed weight image (wq2, wq3)
// ---------------------------------------------------------------------------
__global__ void __launch_bounds__(256) precomp_kernel(
    const float* __restrict__ xin, const float* __restrict__ W1l, const float* __restrict__ b1l,
    const float* __restrict__ W2l, const float* __restrict__ W3l,
    float* __restrict__ Apre, float* __restrict__ Bpre, uint2* __restrict__ wimg)
{
    int part = blockIdx.y;
    int tid = threadIdx.x;

    if (part == 2) {
        int idx = blockIdx.x * 256 + tid;
        if (idx < 4096) {
            int n = idx >> 5, j = idx & 31;
            int k = (j >> 2) * 16 + (j & 3) * 2;
            uint2 v;
            v.x = pk_h2(W2l[k*128 + n],     W2l[(k+1)*128 + n]);
            v.y = pk_h2(W2l[(k+8)*128 + n], W2l[(k+9)*128 + n]);
            wimg[idx] = v;
        } else if (idx < 6144) {
            int i2 = idx - 4096;
            int n = i2 >> 5, j = i2 & 31;
            int k = (j >> 2) * 16 + (j & 3) * 2;
            uint2 v;
            v.x = pk_h2(W3l[k*64 + n],     W3l[(k+1)*64 + n]);
            v.y = pk_h2(W3l[(k+8)*64 + n], W3l[(k+9)*64 + n]);
            wimg[idx] = v;
        }
        return;
    }

    __shared__ float xs[32*64];
    size_t nb = (size_t)blockIdx.x * 32;

    const float4* xg = (const float4*)(xin + nb*64);
    float4* xs4 = (float4*)xs;
#pragma unroll
    for (int i = 0; i < 2; ++i) xs4[tid + i*256] = xg[tid + i*256];
    __syncthreads();

    int tx = tid & 31, ty = tid >> 5;
    unsigned long long acc[4][2];
#pragma unroll
    for (int a = 0; a < 4; ++a) { acc[a][0] = 0ull; acc[a][1] = 0ull; }

    int cbeg = part ? 3 : 0;
    const float* Wb = part ? (W1l + 61*128) : W1l;
#pragma unroll 4
    for (int c = cbeg; c < 64; ++c) {
        ulonglong2 wv = *(const ulonglong2*)(Wb + c*128 + tx*4);
#pragma unroll
        for (int ni = 0; ni < 4; ++ni) {
            unsigned long long av = bcast2(xs[(ty*4+ni)*64 + c]);
            fma2(acc[ni][0], av, wv.x);
            fma2(acc[ni][1], av, wv.y);
        }
    }

    float4 bv = make_float4(0.f,0.f,0.f,0.f);
    float* outp;
    if (part) outp = Bpre;
    else { outp = Apre; bv = *(const float4*)(b1l + tx*4); }
#pragma unroll
    for (int ni = 0; ni < 4; ++ni) {
        float2 p0 = unpk(acc[ni][0]), p1 = unpk(acc[ni][1]);
        float4 r = make_float4(p0.x+bv.x, p0.y+bv.y, p1.x+bv.z, p1.y+bv.w);
        *(float4*)(outp + (nb + ty*4 + ni)*128 + tx*4) = r;
    }
}

// ---------------------------------------------------------------------------
// Fused edge kernel, fp16 MMA m16n8k16:
// gather h1 (fp16) -> MMA (h1@W2) -> silu -> MMA (h2@W3) -> silu -> atomic scatter.
// 128 edges/block, 8 warps, 2 CTAs/SM. h in XOR-swizzled half2 smem words:
// word(e, kw) = e*64 + (kw ^ ((e&7)<<2)), kw = k/2. B via LDG.64 (L1-hot image).
// ---------------------------------------------------------------------------
__global__ void __launch_bounds__(ETHREADS, 2) edge_kernel(
    const float* __restrict__ Apre, const float* __restrict__ Bpre, const float* __restrict__ xin,
    const int* __restrict__ srcp, const int* __restrict__ dstp,
    const float* __restrict__ wdrow, const uint2* __restrict__ wimg, const float* __restrict__ b2l,
    const float* __restrict__ b3l, float* __restrict__ xout)
{
    extern __shared__ unsigned smw[];
    unsigned* hs = smw + SMW_H;                  // [128][64] half2 words
    float* b2s = (float*)(smw + SMW_B2);
    float* b3s = (float*)(smw + SMW_B3);

    const int tid = threadIdx.x;
    const int w = tid >> 5, lane = tid & 31;
    const int g = lane >> 2, tig = lane & 3;
    const int eb = blockIdx.x * EPB;
    const uint2* wq2 = wimg;           // [128][32]
    const uint2* wq3 = wimg + 4096;    // [64][32]

    // stage biases (tiny)
    if (tid < 128) b2s[tid] = b2l[tid];
    else if (tid < 192) b3s[tid-128] = b3l[tid-128];

    // gather h1: warp covers 16 edges, lane covers k-chunk lane*4..lane*4+3
    {
        float4 wd4 = __ldg((const float4*)(wdrow + lane*4));
        int ids = (lane < 16) ? __ldg(srcp + eb + w*16 + lane)
                              : __ldg(dstp + eb + w*16 + (lane - 16));
#pragma unroll 4
        for (int it = 0; it < 16; ++it) {
            int s = __shfl_sync(0xffffffffu, ids, it);
            int d = __shfl_sync(0xffffffffu, ids, 16 + it);
            float4 xs4 = __ldg((const float4*)(xin + (size_t)s*64));
            float4 xd4 = __ldg((const float4*)(xin + (size_t)d*64));
            float dx = xs4.x - xd4.x, dy = xs4.y - xd4.y, dz = xs4.z - xd4.z;
            float dist2 = dx*dx + dy*dy + dz*dz;
            float4 a = __ldg((const float4*)(Apre + (size_t)d*128 + lane*4));
            float4 b = __ldg((const float4*)(Bpre + (size_t)s*128 + lane*4));
            uint2 v;
            v.x = pk_h2(silu_t(a.x + b.x + dist2*wd4.x), silu_t(a.y + b.y + dist2*wd4.y));
            v.y = pk_h2(silu_t(a.z + b.z + dist2*wd4.z), silu_t(a.w + b.w + dist2*wd4.w));
            int e = w*16 + it;
            int kw = (lane*2) ^ ((e & 7) << 2);     // mask bits >=2: pair stays adjacent+aligned
            *(uint2*)(hs + e*64 + kw) = v;
        }
    }
    __syncthreads();

    const int e0 = (w & 3) * 32;
    const int n0 = (w >> 2) * 64;
    const int xm = g << 2;
    const unsigned* hA0 = hs + (e0 + g) * 64;
    const unsigned* hA1 = hs + (e0 + g + 8) * 64;
    const unsigned* hA2 = hs + (e0 + g + 16) * 64;
    const unsigned* hA3 = hs + (e0 + g + 24) * 64;

    // ---- GEMM2: [128e x 128] = h1 @ W2, k=16 per mma ----
    float acc[2][8][4];
#pragma unroll
    for (int mf = 0; mf < 2; ++mf)
#pragma unroll
        for (int nf = 0; nf < 8; ++nf)
#pragma unroll
            for (int q = 0; q < 4; ++q) acc[mf][nf][q] = 0.f;

#pragma unroll
    for (int ks = 0; ks < 8; ++ks) {
        int off1 = (ks*8 + tig) ^ xm;
        int off2 = (ks*8 + tig + 4) ^ xm;
        unsigned a[2][4];
        a[0][0] = hA0[off1]; a[0][1] = hA1[off1];
        a[0][2] = hA0[off2]; a[0][3] = hA1[off2];
        a[1][0] = hA2[off1]; a[1][1] = hA3[off1];
        a[1][2] = hA2[off2]; a[1][3] = hA3[off2];
        int bcol = ks*4 + tig;
#pragma unroll
        for (int nf = 0; nf < 8; ++nf) {
            int n = n0 + nf*8 + g;
            uint2 wv = __ldg(wq2 + n*32 + bcol);
            mma16(acc[0][nf], a[0], wv.x, wv.y);
            mma16(acc[1][nf], a[1], wv.x, wv.y);
        }
    }
    __syncthreads();   // all h1 reads complete before h2 overwrites

    // ---- epilogue1: h2 = fp16(silu(D2 + b2)) back into hs ----
#pragma unroll
    for (int mf = 0; mf < 2; ++mf) {
        int elo = e0 + mf*16 + g;
        unsigned* hlo = hs + elo*64;
        unsigned* hhi = hs + (elo + 8)*64;
#pragma unroll
        for (int nf = 0; nf < 8; ++nf) {
            int n = n0 + nf*8 + 2*tig;
            float bb0 = b2s[n], bb1 = b2s[n+1];
            int kwp = (n >> 1) ^ xm;               // (n0/2 + nf*4 + tig) ^ xm
            hlo[kwp] = pk_h2(silu_t(acc[mf][nf][0] + bb0), silu_t(acc[mf][nf][1] + bb1));
            hhi[kwp] = pk_h2(silu_t(acc[mf][nf][2] + bb0), silu_t(acc[mf][nf][3] + bb1));
        }
    }
    __syncthreads();

    // ---- GEMM3: [128e x 64] = h2 @ W3 ----
    const int n03 = (w >> 2) * 32;
    float acc3[2][4][4];
#pragma unroll
    for (int mf = 0; mf < 2; ++mf)
#pragma unroll
        for (int nf = 0; nf < 4; ++nf)
#pragma unroll
            for (int q = 0; q < 4; ++q) acc3[mf][nf][q] = 0.f;

#pragma unroll
    for (int ks = 0; ks < 8; ++ks) {
        int off1 = (ks*8 + tig) ^ xm;
        int off2 = (ks*8 + tig + 4) ^ xm;
        unsigned a[2][4];
        a[0][0] = hA0[off1]; a[0][1] = hA1[off1];
        a[0][2] = hA0[off2]; a[0][3] = hA1[off2];
        a[1][0] = hA2[off1]; a[1][1] = hA3[off1];
        a[1][2] = hA2[off2]; a[1][3] = hA3[off2];
        int bcol = ks*4 + tig;
#pragma unroll
        for (int nf = 0; nf < 4; ++nf) {
            int n = n03 + nf*8 + g;
            uint2 wv = __ldg(wq3 + n*32 + bcol);
            mma16(acc3[0][nf], a[0], wv.x, wv.y);
            mma16(acc3[1][nf], a[1], wv.x, wv.y);
        }
    }

    // ---- epilogue2: silu(D3 + b3), scalar atomic scatter-add ----
#pragma unroll
    for (int mf = 0; mf < 2; ++mf) {
        int elo = e0 + mf*16 + g;
        int dlo = __ldg(dstp + eb + elo);
        int dhi = __ldg(dstp + eb + elo + 8);
        float* olo = xout + (size_t)dlo*64;
        float* ohi = xout + (size_t)dhi*64;
#pragma unroll
        for (int nf = 0; nf < 4; ++nf) {
            int n = n03 + nf*8 + 2*tig;
            float bb0 = b3s[n], bb1 = b3s[n+1];
            atomicAdd(olo + n,     silu_f(acc3[mf][nf][0] + bb0));
            atomicAdd(olo + n + 1, silu_f(acc3[mf][nf][1] + bb1));
            atomicAdd(ohi + n,     silu_f(acc3[mf][nf][2] + bb0));
            atomicAdd(ohi + n + 1, silu_f(acc3[mf][nf][3] + bb1));
        }
    }
}

// ---------------------------------------------------------------------------
// Pooling + readout MLP (unchanged)
// ---------------------------------------------------------------------------
__global__ void __launch_bounds__(64) pool_head_kernel(
    const float* __restrict__ xf, const int* __restrict__ batch, const float* __restrict__ u,
    const float* __restrict__ LW1, const float* __restrict__ Lb1,
    const float* __restrict__ LW2, const float* __restrict__ Lb2,
    const float* __restrict__ LW3, const float* __restrict__ Lb3,
    float* __restrict__ out)
{
    __shared__ float pooled[194];
    __shared__ float hbuf[64];
    int g = blockIdx.x, f = threadIdx.x;

    int start, end;
    {
        int lo = 0, hi = NN;
        while (lo < hi) { int m = (lo+hi) >> 1; if (batch[m] < g) lo = m+1; else hi = m; }
        start = lo;
        hi = NN;
        while (lo < hi) { int m = (lo+hi) >> 1; if (batch[m] < g+1) lo = m+1; else hi = m; }
        end = lo;
    }

    float s = 0.f, mx = -3.402823466e38f;
    for (int n = start; n < end; ++n) {
        float v = xf[(size_t)n*64 + f];
        s += v; mx = fmaxf(mx, v);
    }
    float cnt = fmaxf((float)(end - start), 1.f);
    pooled[f]      = s;
    pooled[64+f]   = s / cnt;
    pooled[128+f]  = mx;
    if (f < 2) pooled[192+f] = u[g*2+f];
    __syncthreads();

    float a = Lb1[f];
    for (int c = 0; c < 194; ++c) a += pooled[c] * LW1[c*64+f];
    float h = silu_f(a);
    hbuf[f] = h;
    __syncthreads();

    a = Lb2[f];
    for (int c = 0; c < 64; ++c) a += hbuf[c] * LW2[c*64+f];
    h = silu_f(a);
    __syncthreads();
    hbuf[f] = h;
    __syncthreads();

    if (f < 2) {
        a = Lb3[f];
        for (int c = 0; c < 64; ++c) a += hbuf[c] * LW3[c*2+f];
        out[g*2+f] = a;
    }
}

// ---------------------------------------------------------------------------
extern "C" void kernel_launch(void* const* d_in, const int* in_sizes, int n_in,
                              void* d_out, int out_size) {
    const float* x    = (const float*)d_in[0];
    const float* u    = (const float*)d_in[1];
    const int*   ei   = (const int*)d_in[2];
    const int*   batch= (const int*)d_in[3];
    const float* W1   = (const float*)d_in[4];
    const float* b1   = (const float*)d_in[5];
    const float* W2   = (const float*)d_in[6];
    const float* b2   = (const float*)d_in[7];
    const float* W3   = (const float*)d_in[8];
    const float* b3   = (const float*)d_in[9];
    const float* LW1  = (const float*)d_in[10];
    const float* Lb1  = (const float*)d_in[11];
    const float* LW2  = (const float*)d_in[12];
    const float* Lb2  = (const float*)d_in[13];
    const float* LW3  = (const float*)d_in[14];
    const float* Lb3  = (const float*)d_in[15];
    float* out = (float*)d_out;

    float *Apre, *Bpre, *x1, *x2;
    uint2* wimg;
    cudaGetSymbolAddress((void**)&Apre, g_Apre);
    cudaGetSymbolAddress((void**)&Bpre, g_Bpre);
    cudaGetSymbolAddress((void**)&x1,   g_x1);
    cudaGetSymbolAddress((void**)&x2,   g_x2);
    cudaGetSymbolAddress((void**)&wimg, g_wimg);

    cudaFuncSetAttribute(edge_kernel, cudaFuncAttributeMaxDynamicSharedMemorySize, EDGE_SMEM);

    const int* srcp = ei;
    const int* dstp = ei + EE;

    // zero both layer outputs up front (keeps edge_kernel at launch #6 for ncu)
    cudaMemsetAsync(x1, 0, (size_t)NN*FF*sizeof(float));
    cudaMemsetAsync(x2, 0, (size_t)NN*FF*sizeof(float));

    for (int l = 0; l < 2; ++l) {
        const float* xin = l ? (const float*)x1 : x;
        float* xout = l ? x2 : x1;
        precomp_kernel<<<dim3(3125, 3, 1), 256>>>(
            xin, W1 + (size_t)l*126*128, b1 + (size_t)l*128,
            W2 + (size_t)l*128*128, W3 + (size_t)l*128*64,
            Apre, Bpre, wimg);
        edge_kernel<<<EE/EPB, ETHREADS, EDGE_SMEM>>>(
            Apre, Bpre, xin, srcp, dstp,
            W1 + (size_t)l*126*128 + 125*128,
            wimg, b2 + (size_t)l*128,
            b3 + (size_t)l*64, xout);
    }
    pool_head_kernel<<<GG, 64>>>(x2, batch, u, LW1, Lb1, LW2, Lb2, LW3, Lb3, out);
}

// round 14
// speedup vs baseline: 1.8697x; 1.3317x over previous
#include <cuda_runtime.h>
#include <cuda_fp16.h>
#include <math.h>
#include <stdint.h>

#define NN 100000
#define EE 1600000
#define FF 64
#define HH 128
#define GG 256
#define EPB 128
#define ETHREADS 256

// smem layout (words = 32-bit): h tile 128 rows x 64 half2-words, then biases
#define SMW_H 0
#define SMW_B2 8192
#define SMW_B3 8320
#define EDGE_SMEM ((8384) * 4)   // 33536 B -> 2 CTAs/SM (reg-limited)

// scratch (static __device__ arrays: the sanctioned no-alloc workaround)
__device__ __half g_Apre[(size_t)NN*HH];   // fp16 precomputed node terms
__device__ __half g_Bpre[(size_t)NN*HH];
__device__ float g_x1[(size_t)NN*FF];
__device__ float g_x2[(size_t)NN*FF];
// fp16 warp-coalesced weight image (uint2 entries):
//   wq2 [0..4096):  idx = ((tile*8 + nf)*8 + ks)*32 + g*4 + tig
//                   n = tile*64 + nf*8 + g, k = ks*16 + tig*2
//                   entry = halves (W2[k][n], W2[k+1][n], W2[k+8][n], W2[k+9][n])
//   wq3 [4096..6144): idx2 = ((tile*4 + nf)*8 + ks)*32 + g*4 + tig, n = tile*32 + nf*8 + g
__device__ uint2 g_wimg[6144];

__device__ __forceinline__ float silu_f(float v) {
    return __fdividef(v, 1.0f + __expf(-v));
}
// 1-MUFU silu via tanh.approx (err ~2^-10.7, at the level of fp16 rounding of consumers)
__device__ __forceinline__ float silu_t(float v) {
    float t;
    asm("tanh.approx.f32 %0, %1;" : "=f"(t) : "f"(0.5f * v));
    return 0.5f * v * (1.0f + t);
}
__device__ __forceinline__ unsigned pk_h2(float a, float b) {
    __half2 h = __floats2half2_rn(a, b);
    return *reinterpret_cast<unsigned*>(&h);
}
__device__ __forceinline__ float2 uph2(unsigned u) {
    __half2 h = *reinterpret_cast<__half2*>(&u);
    return __half22float2(h);
}
// m16n8k16 fp16 MMA, fp32 accumulate
__device__ __forceinline__ void mma16(float* d, const unsigned* a, unsigned b0, unsigned b1) {
    asm volatile("mma.sync.aligned.m16n8k16.row.col.f32.f16.f16.f32 "
        "{%0,%1,%2,%3}, {%4,%5,%6,%7}, {%8,%9}, {%0,%1,%2,%3};"
        : "+f"(d[0]), "+f"(d[1]), "+f"(d[2]), "+f"(d[3])
        : "r"(a[0]), "r"(a[1]), "r"(a[2]), "r"(a[3]), "r"(b0), "r"(b1));
}
// packed f32x2 helpers (for precomp)
__device__ __forceinline__ void fma2(unsigned long long& d, unsigned long long a, unsigned long long b) {
    asm("fma.rn.f32x2 %0, %1, %2, %0;" : "+l"(d) : "l"(a), "l"(b));
}
__device__ __forceinline__ unsigned long long bcast2(float a) {
    unsigned long long r; asm("mov.b64 %0, {%1, %1};" : "=l"(r) : "f"(a)); return r;
}
__device__ __forceinline__ float2 unpk(unsigned long long v) {
    float2 r; asm("mov.b64 {%0, %1}, %2;" : "=f"(r.x), "=f"(r.y) : "l"(v)); return r;
}

// ---------------------------------------------------------------------------
// Combined precompute:
//   part 0: Apre = fp16(x @ W1[0:64] + b1)
//   part 1: Bpre = fp16(x[:,3:] @ W1[64:125])
//   part 2: warp-coalesced fp16 weight image (wq2, wq3)
// ---------------------------------------------------------------------------
__global__ void __launch_bounds__(256) precomp_kernel(
    const float* __restrict__ xin, const float* __restrict__ W1l, const float* __restrict__ b1l,
    const float* __restrict__ W2l, const float* __restrict__ W3l,
    __half* __restrict__ Apre, __half* __restrict__ Bpre, uint2* __restrict__ wimg)
{
    int part = blockIdx.y;
    int tid = threadIdx.x;

    if (part == 2) {
        int idx = blockIdx.x * 256 + tid;
        if (idx < 4096) {
            int rem = idx & 2047;
            int tile = idx >> 11;
            int nf = rem >> 8, ks = (rem >> 5) & 7, gg = (rem >> 2) & 7, tg = rem & 3;
            int n = tile*64 + nf*8 + gg;
            int k = ks*16 + tg*2;
            uint2 v;
            v.x = pk_h2(W2l[k*128 + n],     W2l[(k+1)*128 + n]);
            v.y = pk_h2(W2l[(k+8)*128 + n], W2l[(k+9)*128 + n]);
            wimg[idx] = v;
        } else if (idx < 6144) {
            int i2 = idx - 4096;
            int rem = i2 & 1023;
            int tile = i2 >> 10;
            int nf = rem >> 8, ks = (rem >> 5) & 7, gg = (rem >> 2) & 7, tg = rem & 3;
            int n = tile*32 + nf*8 + gg;
            int k = ks*16 + tg*2;
            uint2 v;
            v.x = pk_h2(W3l[k*64 + n],     W3l[(k+1)*64 + n]);
            v.y = pk_h2(W3l[(k+8)*64 + n], W3l[(k+9)*64 + n]);
            wimg[4096 + i2] = v;
        }
        return;
    }

    __shared__ float xs[32*64];
    size_t nb = (size_t)blockIdx.x * 32;

    const float4* xg = (const float4*)(xin + nb*64);
    float4* xs4 = (float4*)xs;
#pragma unroll
    for (int i = 0; i < 2; ++i) xs4[tid + i*256] = xg[tid + i*256];
    __syncthreads();

    int tx = tid & 31, ty = tid >> 5;
    unsigned long long acc[4][2];
#pragma unroll
    for (int a = 0; a < 4; ++a) { acc[a][0] = 0ull; acc[a][1] = 0ull; }

    int cbeg = part ? 3 : 0;
    const float* Wb = part ? (W1l + 61*128) : W1l;
#pragma unroll 4
    for (int c = cbeg; c < 64; ++c) {
        ulonglong2 wv = *(const ulonglong2*)(Wb + c*128 + tx*4);
#pragma unroll
        for (int ni = 0; ni < 4; ++ni) {
            unsigned long long av = bcast2(xs[(ty*4+ni)*64 + c]);
            fma2(acc[ni][0], av, wv.x);
            fma2(acc[ni][1], av, wv.y);
        }
    }

    float4 bv = make_float4(0.f,0.f,0.f,0.f);
    __half* outp;
    if (part) outp = Bpre;
    else { outp = Apre; bv = *(const float4*)(b1l + tx*4); }
    uint2* outu = (uint2*)outp;
#pragma unroll
    for (int ni = 0; ni < 4; ++ni) {
        float2 p0 = unpk(acc[ni][0]), p1 = unpk(acc[ni][1]);
        uint2 r;
        r.x = pk_h2(p0.x+bv.x, p0.y+bv.y);
        r.y = pk_h2(p1.x+bv.z, p1.y+bv.w);
        outu[(nb + ty*4 + ni)*32 + tx] = r;
    }
}

// ---------------------------------------------------------------------------
// Fused edge kernel, fp16 MMA m16n8k16:
// gather h1 (fp16, from fp16 Apre/Bpre) -> MMA (h1@W2) -> silu -> MMA (h2@W3)
// -> silu -> fp32 atomic scatter. 128 edges/block, 8 warps, 2 CTAs/SM.
// h in XOR-swizzled half2 smem words; B via coalesced LDG.64 (L1-hot image).
// ---------------------------------------------------------------------------
__global__ void __launch_bounds__(ETHREADS, 2) edge_kernel(
    const __half* __restrict__ Apre, const __half* __restrict__ Bpre, const float* __restrict__ xin,
    const int* __restrict__ srcp, const int* __restrict__ dstp,
    const float* __restrict__ wdrow, const uint2* __restrict__ wimg, const float* __restrict__ b2l,
    const float* __restrict__ b3l, float* __restrict__ xout)
{
    extern __shared__ unsigned smw[];
    unsigned* hs = smw + SMW_H;                  // [128][64] half2 words
    float* b2s = (float*)(smw + SMW_B2);
    float* b3s = (float*)(smw + SMW_B3);

    const int tid = threadIdx.x;
    const int w = tid >> 5, lane = tid & 31;
    const int g = lane >> 2, tig = lane & 3;
    const int eb = blockIdx.x * EPB;

    // stage biases (tiny)
    if (tid < 128) b2s[tid] = b2l[tid];
    else if (tid < 192) b3s[tid-128] = b3l[tid-128];

    // gather h1: warp covers 16 edges, lane covers k-chunk lane*4..lane*4+3
    {
        float4 wd4 = __ldg((const float4*)(wdrow + lane*4));
        int ids = (lane < 16) ? __ldg(srcp + eb + w*16 + lane)
                              : __ldg(dstp + eb + w*16 + (lane - 16));
        const uint2* Au = (const uint2*)Apre;
        const uint2* Bu = (const uint2*)Bpre;
#pragma unroll 4
        for (int it = 0; it < 16; ++it) {
            int s = __shfl_sync(0xffffffffu, ids, it);
            int d = __shfl_sync(0xffffffffu, ids, 16 + it);
            float4 xs4 = __ldg((const float4*)(xin + (size_t)s*64));
            float4 xd4 = __ldg((const float4*)(xin + (size_t)d*64));
            float dx = xs4.x - xd4.x, dy = xs4.y - xd4.y, dz = xs4.z - xd4.z;
            float dist2 = dx*dx + dy*dy + dz*dz;
            uint2 au = __ldg(Au + (size_t)d*32 + lane);
            uint2 bu = __ldg(Bu + (size_t)s*32 + lane);
            float2 a01 = uph2(au.x), a23 = uph2(au.y);
            float2 b01 = uph2(bu.x), b23 = uph2(bu.y);
            uint2 v;
            v.x = pk_h2(silu_t(a01.x + b01.x + dist2*wd4.x),
                        silu_t(a01.y + b01.y + dist2*wd4.y));
            v.y = pk_h2(silu_t(a23.x + b23.x + dist2*wd4.z),
                        silu_t(a23.y + b23.y + dist2*wd4.w));
            int e = w*16 + it;
            int kw = (lane*2) ^ ((e & 7) << 2);     // mask bits >=2: pair stays adjacent+aligned
            *(uint2*)(hs + e*64 + kw) = v;
        }
    }
    __syncthreads();

    const int e0 = (w & 3) * 32;
    const int n0 = (w >> 2) * 64;
    const int xm = g << 2;
    const unsigned* hA0 = hs + (e0 + g) * 64;
    const unsigned* hA1 = hs + (e0 + g + 8) * 64;
    const unsigned* hA2 = hs + (e0 + g + 16) * 64;
    const unsigned* hA3 = hs + (e0 + g + 24) * 64;
    const uint2* w2b = wimg + (w >> 2) * 2048 + lane;          // coalesced tile base
    const uint2* w3b = wimg + 4096 + (w >> 2) * 1024 + lane;

    // ---- GEMM2: [128e x 128] = h1 @ W2, k=16 per mma ----
    float acc[2][8][4];
#pragma unroll
    for (int mf = 0; mf < 2; ++mf)
#pragma unroll
        for (int nf = 0; nf < 8; ++nf)
#pragma unroll
            for (int q = 0; q < 4; ++q) acc[mf][nf][q] = 0.f;

#pragma unroll
    for (int ks = 0; ks < 8; ++ks) {
        int off1 = (ks*8 + tig) ^ xm;
        int off2 = (ks*8 + tig + 4) ^ xm;
        unsigned a[2][4];
        a[0][0] = hA0[off1]; a[0][1] = hA1[off1];
        a[0][2] = hA0[off2]; a[0][3] = hA1[off2];
        a[1][0] = hA2[off1]; a[1][1] = hA3[off1];
        a[1][2] = hA2[off2]; a[1][3] = hA3[off2];
#pragma unroll
        for (int nf = 0; nf < 8; ++nf) {
            uint2 wv = __ldg(w2b + nf*256 + ks*32);
            mma16(acc[0][nf], a[0], wv.x, wv.y);
            mma16(acc[1][nf], a[1], wv.x, wv.y);
        }
    }
    __syncthreads();   // all h1 reads complete before h2 overwrites

    // ---- epilogue1: h2 = fp16(silu(D2 + b2)) back into hs ----
#pragma unroll
    for (int mf = 0; mf < 2; ++mf) {
        int elo = e0 + mf*16 + g;
        unsigned* hlo = hs + elo*64;
        unsigned* hhi = hs + (elo + 8)*64;
#pragma unroll
        for (int nf = 0; nf < 8; ++nf) {
            int n = n0 + nf*8 + 2*tig;
            float bb0 = b2s[n], bb1 = b2s[n+1];
            int kwp = (n >> 1) ^ xm;               // (n0/2 + nf*4 + tig) ^ xm
            hlo[kwp] = pk_h2(silu_t(acc[mf][nf][0] + bb0), silu_t(acc[mf][nf][1] + bb1));
            hhi[kwp] = pk_h2(silu_t(acc[mf][nf][2] + bb0), silu_t(acc[mf][nf][3] + bb1));
        }
    }
    __syncthreads();

    // ---- GEMM3: [128e x 64] = h2 @ W3 ----
    const int n03 = (w >> 2) * 32;
    float acc3[2][4][4];
#pragma unroll
    for (int mf = 0; mf < 2; ++mf)
#pragma unroll
        for (int nf = 0; nf < 4; ++nf)
#pragma unroll
            for (int q = 0; q < 4; ++q) acc3[mf][nf][q] = 0.f;

#pragma unroll
    for (int ks = 0; ks < 8; ++ks) {
        int off1 = (ks*8 + tig) ^ xm;
        int off2 = (ks*8 + tig + 4) ^ xm;
        unsigned a[2][4];
        a[0][0] = hA0[off1]; a[0][1] = hA1[off1];
        a[0][2] = hA0[off2]; a[0][3] = hA1[off2];
        a[1][0] = hA2[off1]; a[1][1] = hA3[off1];
        a[1][2] = hA2[off2]; a[1][3] = hA3[off2];
#pragma unroll
        for (int nf = 0; nf < 4; ++nf) {
            uint2 wv = __ldg(w3b + nf*256 + ks*32);
            mma16(acc3[0][nf], a[0], wv.x, wv.y);
            mma16(acc3[1][nf], a[1], wv.x, wv.y);
        }
    }

    // ---- epilogue2: silu(D3 + b3), scalar atomic scatter-add ----
#pragma unroll
    for (int mf = 0; mf < 2; ++mf) {
        int elo = e0 + mf*16 + g;
        int dlo = __ldg(dstp + eb + elo);
        int dhi = __ldg(dstp + eb + elo + 8);
        float* olo = xout + (size_t)dlo*64;
        float* ohi = xout + (size_t)dhi*64;
#pragma unroll
        for (int nf = 0; nf < 4; ++nf) {
            int n = n03 + nf*8 + 2*tig;
            float bb0 = b3s[n], bb1 = b3s[n+1];
            atomicAdd(olo + n,     silu_f(acc3[mf][nf][0] + bb0));
            atomicAdd(olo + n + 1, silu_f(acc3[mf][nf][1] + bb1));
            atomicAdd(ohi + n,     silu_f(acc3[mf][nf][2] + bb0));
            atomicAdd(ohi + n + 1, silu_f(acc3[mf][nf][3] + bb1));
        }
    }
}

// ---------------------------------------------------------------------------
// Pooling + readout MLP (unchanged)
// ---------------------------------------------------------------------------
__global__ void __launch_bounds__(64) pool_head_kernel(
    const float* __restrict__ xf, const int* __restrict__ batch, const float* __restrict__ u,
    const float* __restrict__ LW1, const float* __restrict__ Lb1,
    const float* __restrict__ LW2, const float* __restrict__ Lb2,
    const float* __restrict__ LW3, const float* __restrict__ Lb3,
    float* __restrict__ out)
{
    __shared__ float pooled[194];
    __shared__ float hbuf[64];
    int g = blockIdx.x, f = threadIdx.x;

    int start, end;
    {
        int lo = 0, hi = NN;
        while (lo < hi) { int m = (lo+hi) >> 1; if (batch[m] < g) lo = m+1; else hi = m; }
        start = lo;
        hi = NN;
        while (lo < hi) { int m = (lo+hi) >> 1; if (batch[m] < g+1) lo = m+1; else hi = m; }
        end = lo;
    }

    float s = 0.f, mx = -3.402823466e38f;
    for (int n = start; n < end; ++n) {
        float v = xf[(size_t)n*64 + f];
        s += v; mx = fmaxf(mx, v);
    }
    float cnt = fmaxf((float)(end - start), 1.f);
    pooled[f]      = s;
    pooled[64+f]   = s / cnt;
    pooled[128+f]  = mx;
    if (f < 2) pooled[192+f] = u[g*2+f];
    __syncthreads();

    float a = Lb1[f];
    for (int c = 0; c < 194; ++c) a += pooled[c] * LW1[c*64+f];
    float h = silu_f(a);
    hbuf[f] = h;
    __syncthreads();

    a = Lb2[f];
    for (int c = 0; c < 64; ++c) a += hbuf[c] * LW2[c*64+f];
    h = silu_f(a);
    __syncthreads();
    hbuf[f] = h;
    __syncthreads();

    if (f < 2) {
        a = Lb3[f];
        for (int c = 0; c < 64; ++c) a += hbuf[c] * LW3[c*2+f];
        out[g*2+f] = a;
    }
}

// ---------------------------------------------------------------------------
extern "C" void kernel_launch(void* const* d_in, const int* in_sizes, int n_in,
                              void* d_out, int out_size) {
    const float* x    = (const float*)d_in[0];
    const float* u    = (const float*)d_in[1];
    const int*   ei   = (const int*)d_in[2];
    const int*   batch= (const int*)d_in[3];
    const float* W1   = (const float*)d_in[4];
    const float* b1   = (const float*)d_in[5];
    const float* W2   = (const float*)d_in[6];
    const float* b2   = (const float*)d_in[7];
    const float* W3   = (const float*)d_in[8];
    const float* b3   = (const float*)d_in[9];
    const float* LW1  = (const float*)d_in[10];
    const float* Lb1  = (const float*)d_in[11];
    const float* LW2  = (const float*)d_in[12];
    const float* Lb2  = (const float*)d_in[13];
    const float* LW3  = (const float*)d_in[14];
    const float* Lb3  = (const float*)d_in[15];
    float* out = (float*)d_out;

    __half *Apre, *Bpre;
    float *x1, *x2;
    uint2* wimg;
    cudaGetSymbolAddress((void**)&Apre, g_Apre);
    cudaGetSymbolAddress((void**)&Bpre, g_Bpre);
    cudaGetSymbolAddress((void**)&x1,   g_x1);
    cudaGetSymbolAddress((void**)&x2,   g_x2);
    cudaGetSymbolAddress((void**)&wimg, g_wimg);

    cudaFuncSetAttribute(edge_kernel, cudaFuncAttributeMaxDynamicSharedMemorySize, EDGE_SMEM);

    const int* srcp = ei;
    const int* dstp = ei + EE;

    // zero both layer outputs up front (keeps edge_kernel at launch #6 for ncu)
    cudaMemsetAsync(x1, 0, (size_t)NN*FF*sizeof(float));
    cudaMemsetAsync(x2, 0, (size_t)NN*FF*sizeof(float));

    for (int l = 0; l < 2; ++l) {
        const float* xin = l ? (const float*)x1 : x;
        float* xout = l ? x2 : x1;
        precomp_kernel<<<dim3(3125, 3, 1), 256>>>(
            xin, W1 + (size_t)l*126*128, b1 + (size_t)l*128,
            W2 + (size_t)l*128*128, W3 + (size_t)l*128*64,
            Apre, Bpre, wimg);
        edge_kernel<<<EE/EPB, ETHREADS, EDGE_SMEM>>>(
            Apre, Bpre, xin, srcp, dstp,
            W1 + (size_t)l*126*128 + 125*128,
            wimg, b2 + (size_t)l*128,
            b3 + (size_t)l*64, xout);
    }
    pool_head_kernel<<<GG, 64>>>(x2, batch, u, LW1, Lb1, LW2, Lb2, LW3, Lb3, out);
}

// round 15
// speedup vs baseline: 1.9202x; 1.0270x over previous
#include <cuda_runtime.h>
#include <cuda_fp16.h>
#include <math.h>
#include <stdint.h>

#define NN 100000
#define EE 1600000
#define FF 64
#define HH 128
#define GG 256
#define EPB 128
#define ETHREADS 256

// smem layout (words = 32-bit): h tile 128 rows x 64 half2-words, then biases
#define SMW_H 0
#define SMW_B2 8192
#define SMW_B3 8320
#define EDGE_SMEM ((8384) * 4)   // 33536 B -> 2 CTAs/SM (reg-limited)

// scratch (static __device__ arrays: the sanctioned no-alloc workaround)
__device__ __half g_Apre[(size_t)NN*HH];   // fp16 precomputed node terms
__device__ __half g_Bpre[(size_t)NN*HH];
__device__ float g_x1[(size_t)NN*FF];
__device__ float g_x2[(size_t)NN*FF];
// fp16 warp-coalesced weight image (uint2 entries):
//   wq2 [0..4096):  idx = ((tile*8 + nf)*8 + ks)*32 + g*4 + tig
//                   n = tile*64 + nf*8 + g, k = ks*16 + tig*2
//                   entry = halves (W2[k][n], W2[k+1][n], W2[k+8][n], W2[k+9][n])
//   wq3 [4096..6144): idx2 = ((tile*4 + nf)*8 + ks)*32 + g*4 + tig, n = tile*32 + nf*8 + g
__device__ uint2 g_wimg[6144];

__device__ __forceinline__ float silu_f(float v) {
    return __fdividef(v, 1.0f + __expf(-v));
}
// 1-MUFU silu via tanh.approx (err ~2^-10.7, at the level of fp16 rounding of consumers)
__device__ __forceinline__ float silu_t(float v) {
    float t;
    asm("tanh.approx.f32 %0, %1;" : "=f"(t) : "f"(0.5f * v));
    return 0.5f * v * (1.0f + t);
}
__device__ __forceinline__ unsigned pk_h2(float a, float b) {
    __half2 h = __floats2half2_rn(a, b);
    return *reinterpret_cast<unsigned*>(&h);
}
__device__ __forceinline__ float2 uph2(unsigned u) {
    __half2 h = *reinterpret_cast<__half2*>(&u);
    return __half22float2(h);
}
// m16n8k16 fp16 MMA, fp32 accumulate
__device__ __forceinline__ void mma16(float* d, const unsigned* a, unsigned b0, unsigned b1) {
    asm volatile("mma.sync.aligned.m16n8k16.row.col.f32.f16.f16.f32 "
        "{%0,%1,%2,%3}, {%4,%5,%6,%7}, {%8,%9}, {%0,%1,%2,%3};"
        : "+f"(d[0]), "+f"(d[1]), "+f"(d[2]), "+f"(d[3])
        : "r"(a[0]), "r"(a[1]), "r"(a[2]), "r"(a[3]), "r"(b0), "r"(b1));
}
// packed f32x2 helpers (for precomp)
__device__ __forceinline__ void fma2(unsigned long long& d, unsigned long long a, unsigned long long b) {
    asm("fma.rn.f32x2 %0, %1, %2, %0;" : "+l"(d) : "l"(a), "l"(b));
}
__device__ __forceinline__ unsigned long long bcast2(float a) {
    unsigned long long r; asm("mov.b64 %0, {%1, %1};" : "=l"(r) : "f"(a)); return r;
}
__device__ __forceinline__ float2 unpk(unsigned long long v) {
    float2 r; asm("mov.b64 {%0, %1}, %2;" : "=f"(r.x), "=f"(r.y) : "l"(v)); return r;
}

// ---------------------------------------------------------------------------
// Combined precompute:
//   part 0: Apre = fp16(x @ W1[0:64] + b1)
//   part 1: Bpre = fp16(x[:,3:] @ W1[64:125])
//   part 2: warp-coalesced fp16 weight image (wq2, wq3)
// ---------------------------------------------------------------------------
__global__ void __launch_bounds__(256) precomp_kernel(
    const float* __restrict__ xin, const float* __restrict__ W1l, const float* __restrict__ b1l,
    const float* __restrict__ W2l, const float* __restrict__ W3l,
    __half* __restrict__ Apre, __half* __restrict__ Bpre, uint2* __restrict__ wimg)
{
    int part = blockIdx.y;
    int tid = threadIdx.x;

    if (part == 2) {
        int idx = blockIdx.x * 256 + tid;
        if (idx < 4096) {
            int rem = idx & 2047;
            int tile = idx >> 11;
            int nf = rem >> 8, ks = (rem >> 5) & 7, gg = (rem >> 2) & 7, tg = rem & 3;
            int n = tile*64 + nf*8 + gg;
            int k = ks*16 + tg*2;
            uint2 v;
            v.x = pk_h2(W2l[k*128 + n],     W2l[(k+1)*128 + n]);
            v.y = pk_h2(W2l[(k+8)*128 + n], W2l[(k+9)*128 + n]);
            wimg[idx] = v;
        } else if (idx < 6144) {
            int i2 = idx - 4096;
            int rem = i2 & 1023;
            int tile = i2 >> 10;
            int nf = rem >> 8, ks = (rem >> 5) & 7, gg = (rem >> 2) & 7, tg = rem & 3;
            int n = tile*32 + nf*8 + gg;
            int k = ks*16 + tg*2;
            uint2 v;
            v.x = pk_h2(W3l[k*64 + n],     W3l[(k+1)*64 + n]);
            v.y = pk_h2(W3l[(k+8)*64 + n], W3l[(k+9)*64 + n]);
            wimg[4096 + i2] = v;
        }
        return;
    }

    __shared__ float xs[32*64];
    size_t nb = (size_t)blockIdx.x * 32;

    const float4* xg = (const float4*)(xin + nb*64);
    float4* xs4 = (float4*)xs;
#pragma unroll
    for (int i = 0; i < 2; ++i) xs4[tid + i*256] = xg[tid + i*256];
    __syncthreads();

    int tx = tid & 31, ty = tid >> 5;
    unsigned long long acc[4][2];
#pragma unroll
    for (int a = 0; a < 4; ++a) { acc[a][0] = 0ull; acc[a][1] = 0ull; }

    int cbeg = part ? 3 : 0;
    const float* Wb = part ? (W1l + 61*128) : W1l;
#pragma unroll 4
    for (int c = cbeg; c < 64; ++c) {
        ulonglong2 wv = *(const ulonglong2*)(Wb + c*128 + tx*4);
#pragma unroll
        for (int ni = 0; ni < 4; ++ni) {
            unsigned long long av = bcast2(xs[(ty*4+ni)*64 + c]);
            fma2(acc[ni][0], av, wv.x);
            fma2(acc[ni][1], av, wv.y);
        }
    }

    float4 bv = make_float4(0.f,0.f,0.f,0.f);
    __half* outp;
    if (part) outp = Bpre;
    else { outp = Apre; bv = *(const float4*)(b1l + tx*4); }
    uint2* outu = (uint2*)outp;
#pragma unroll
    for (int ni = 0; ni < 4; ++ni) {
        float2 p0 = unpk(acc[ni][0]), p1 = unpk(acc[ni][1]);
        uint2 r;
        r.x = pk_h2(p0.x+bv.x, p0.y+bv.y);
        r.y = pk_h2(p1.x+bv.z, p1.y+bv.w);
        outu[(nb + ty*4 + ni)*32 + tx] = r;
    }
}

// ---------------------------------------------------------------------------
// Fused edge kernel, fp16 MMA m16n8k16:
// gather h1 (fp16) -> MMA (h1@W2) -> silu -> MMA (h2@W3) -> silu ->
// smem-staged COALESCED atomic scatter. 128 edges/block, 8 warps, 2 CTAs/SM.
// ---------------------------------------------------------------------------
__global__ void __launch_bounds__(ETHREADS, 2) edge_kernel(
    const __half* __restrict__ Apre, const __half* __restrict__ Bpre, const float* __restrict__ xin,
    const int* __restrict__ srcp, const int* __restrict__ dstp,
    const float* __restrict__ wdrow, const uint2* __restrict__ wimg, const float* __restrict__ b2l,
    const float* __restrict__ b3l, float* __restrict__ xout)
{
    extern __shared__ unsigned smw[];
    unsigned* hs = smw + SMW_H;                  // [128][64] half2 words
    float* b2s = (float*)(smw + SMW_B2);
    float* b3s = (float*)(smw + SMW_B3);

    const int tid = threadIdx.x;
    const int w = tid >> 5, lane = tid & 31;
    const int g = lane >> 2, tig = lane & 3;
    const int eb = blockIdx.x * EPB;

    // stage biases (tiny)
    if (tid < 128) b2s[tid] = b2l[tid];
    else if (tid < 192) b3s[tid-128] = b3l[tid-128];

    // gather h1: warp covers 16 edges, lane covers k-chunk lane*4..lane*4+3
    {
        float4 wd4 = __ldg((const float4*)(wdrow + lane*4));
        int ids = (lane < 16) ? __ldg(srcp + eb + w*16 + lane)
                              : __ldg(dstp + eb + w*16 + (lane - 16));
        const uint2* Au = (const uint2*)Apre;
        const uint2* Bu = (const uint2*)Bpre;
#pragma unroll 4
        for (int it = 0; it < 16; ++it) {
            int s = __shfl_sync(0xffffffffu, ids, it);
            int d = __shfl_sync(0xffffffffu, ids, 16 + it);
            float4 xs4 = __ldg((const float4*)(xin + (size_t)s*64));
            float4 xd4 = __ldg((const float4*)(xin + (size_t)d*64));
            float dx = xs4.x - xd4.x, dy = xs4.y - xd4.y, dz = xs4.z - xd4.z;
            float dist2 = dx*dx + dy*dy + dz*dz;
            uint2 au = __ldg(Au + (size_t)d*32 + lane);
            uint2 bu = __ldg(Bu + (size_t)s*32 + lane);
            float2 a01 = uph2(au.x), a23 = uph2(au.y);
            float2 b01 = uph2(bu.x), b23 = uph2(bu.y);
            uint2 v;
            v.x = pk_h2(silu_t(a01.x + b01.x + dist2*wd4.x),
                        silu_t(a01.y + b01.y + dist2*wd4.y));
            v.y = pk_h2(silu_t(a23.x + b23.x + dist2*wd4.z),
                        silu_t(a23.y + b23.y + dist2*wd4.w));
            int e = w*16 + it;
            int kw = (lane*2) ^ ((e & 7) << 2);     // mask bits >=2: pair stays adjacent+aligned
            *(uint2*)(hs + e*64 + kw) = v;
        }
    }
    __syncthreads();

    const int e0 = (w & 3) * 32;
    const int n0 = (w >> 2) * 64;
    const int xm = g << 2;
    const unsigned* hA0 = hs + (e0 + g) * 64;
    const unsigned* hA1 = hs + (e0 + g + 8) * 64;
    const unsigned* hA2 = hs + (e0 + g + 16) * 64;
    const unsigned* hA3 = hs + (e0 + g + 24) * 64;
    const uint2* w2b = wimg + (w >> 2) * 2048 + lane;          // coalesced tile base
    const uint2* w3b = wimg + 4096 + (w >> 2) * 1024 + lane;

    // ---- GEMM2: [128e x 128] = h1 @ W2, k=16 per mma ----
    float acc[2][8][4];
#pragma unroll
    for (int mf = 0; mf < 2; ++mf)
#pragma unroll
        for (int nf = 0; nf < 8; ++nf)
#pragma unroll
            for (int q = 0; q < 4; ++q) acc[mf][nf][q] = 0.f;

#pragma unroll
    for (int ks = 0; ks < 8; ++ks) {
        int off1 = (ks*8 + tig) ^ xm;
        int off2 = (ks*8 + tig + 4) ^ xm;
        unsigned a[2][4];
        a[0][0] = hA0[off1]; a[0][1] = hA1[off1];
        a[0][2] = hA0[off2]; a[0][3] = hA1[off2];
        a[1][0] = hA2[off1]; a[1][1] = hA3[off1];
        a[1][2] = hA2[off2]; a[1][3] = hA3[off2];
#pragma unroll
        for (int nf = 0; nf < 8; ++nf) {
            uint2 wv = __ldg(w2b + nf*256 + ks*32);
            mma16(acc[0][nf], a[0], wv.x, wv.y);
            mma16(acc[1][nf], a[1], wv.x, wv.y);
        }
    }
    __syncthreads();   // all h1 reads complete before h2 overwrites

    // ---- epilogue1: h2 = fp16(silu(D2 + b2)) back into hs ----
#pragma unroll
    for (int mf = 0; mf < 2; ++mf) {
        int elo = e0 + mf*16 + g;
        unsigned* hlo = hs + elo*64;
        unsigned* hhi = hs + (elo + 8)*64;
#pragma unroll
        for (int nf = 0; nf < 8; ++nf) {
            int n = n0 + nf*8 + 2*tig;
            float bb0 = b2s[n], bb1 = b2s[n+1];
            int kwp = (n >> 1) ^ xm;               // (n0/2 + nf*4 + tig) ^ xm
            hlo[kwp] = pk_h2(silu_t(acc[mf][nf][0] + bb0), silu_t(acc[mf][nf][1] + bb1));
            hhi[kwp] = pk_h2(silu_t(acc[mf][nf][2] + bb0), silu_t(acc[mf][nf][3] + bb1));
        }
    }
    __syncthreads();

    // ---- GEMM3: [128e x 64] = h2 @ W3 ----
    const int n03 = (w >> 2) * 32;
    float acc3[2][4][4];
#pragma unroll
    for (int mf = 0; mf < 2; ++mf)
#pragma unroll
        for (int nf = 0; nf < 4; ++nf)
#pragma unroll
            for (int q = 0; q < 4; ++q) acc3[mf][nf][q] = 0.f;

#pragma unroll
    for (int ks = 0; ks < 8; ++ks) {
        int off1 = (ks*8 + tig) ^ xm;
        int off2 = (ks*8 + tig + 4) ^ xm;
        unsigned a[2][4];
        a[0][0] = hA0[off1]; a[0][1] = hA1[off1];
        a[0][2] = hA0[off2]; a[0][3] = hA1[off2];
        a[1][0] = hA2[off1]; a[1][1] = hA3[off1];
        a[1][2] = hA2[off2]; a[1][3] = hA3[off2];
#pragma unroll
        for (int nf = 0; nf < 4; ++nf) {
            uint2 wv = __ldg(w3b + nf*256 + ks*32);
            mma16(acc3[0][nf], a[0], wv.x, wv.y);
            mma16(acc3[1][nf], a[1], wv.x, wv.y);
        }
    }
    __syncthreads();   // all h2 reads complete before fp32 staging overwrites hs

    // ---- epilogue2a: stage m = silu(D3 + b3) as fp32 into hs, col-swizzled ----
    // ms[e][c] at word e*64 + (c ^ ((e&7)<<3)); per-row permutation, so the two
    // n-half warps (same rows, disjoint c) never collide.
    {
        float* ms = (float*)hs;
#pragma unroll
        for (int mf = 0; mf < 2; ++mf) {
            int r1 = e0 + mf*16 + g;           // r1 & 7 == g
            int r2 = r1 + 8;
#pragma unroll
            for (int nf = 0; nf < 4; ++nf) {
                int c0 = n03 + nf*8 + 2*tig;
                float bb0 = b3s[c0], bb1 = b3s[c0+1];
                float2 v1 = make_float2(silu_f(acc3[mf][nf][0] + bb0),
                                        silu_f(acc3[mf][nf][1] + bb1));
                float2 v2 = make_float2(silu_f(acc3[mf][nf][2] + bb0),
                                        silu_f(acc3[mf][nf][3] + bb1));
                int sc = c0 ^ (g << 3);
                *(float2*)(ms + r1*64 + sc) = v1;
                *(float2*)(ms + r2*64 + sc) = v2;
            }
        }
    }
    __syncthreads();

    // ---- epilogue2b: coalesced scatter — per edge, 2 REDs of 32 consecutive lanes ----
    {
        const float* ms = (const float*)hs;
        int dstid = __ldg(dstp + eb + w*16 + (lane & 15));
#pragma unroll 4
        for (int it = 0; it < 16; ++it) {
            int e = w*16 + it;
            int d = __shfl_sync(0xffffffffu, dstid, it);
            int msk = (e & 7) << 3;
            float v0 = ms[e*64 + (lane ^ msk)];
            float v1 = ms[e*64 + ((lane + 32) ^ msk)];
            float* op = xout + (size_t)d*64;
            atomicAdd(op + lane, v0);
            atomicAdd(op + lane + 32, v1);
        }
    }
}

// ---------------------------------------------------------------------------
// Pooling + readout MLP (unchanged)
// ---------------------------------------------------------------------------
__global__ void __launch_bounds__(64) pool_head_kernel(
    const float* __restrict__ xf, const int* __restrict__ batch, const float* __restrict__ u,
    const float* __restrict__ LW1, const float* __restrict__ Lb1,
    const float* __restrict__ LW2, const float* __restrict__ Lb2,
    const float* __restrict__ LW3, const float* __restrict__ Lb3,
    float* __restrict__ out)
{
    __shared__ float pooled[194];
    __shared__ float hbuf[64];
    int g = blockIdx.x, f = threadIdx.x;

    int start, end;
    {
        int lo = 0, hi = NN;
        while (lo < hi) { int m = (lo+hi) >> 1; if (batch[m] < g) lo = m+1; else hi = m; }
        start = lo;
        hi = NN;
        while (lo < hi) { int m = (lo+hi) >> 1; if (batch[m] < g+1) lo = m+1; else hi = m; }
        end = lo;
    }

    float s = 0.f, mx = -3.402823466e38f;
    for (int n = start; n < end; ++n) {
        float v = xf[(size_t)n*64 + f];
        s += v; mx = fmaxf(mx, v);
    }
    float cnt = fmaxf((float)(end - start), 1.f);
    pooled[f]      = s;
    pooled[64+f]   = s / cnt;
    pooled[128+f]  = mx;
    if (f < 2) pooled[192+f] = u[g*2+f];
    __syncthreads();

    float a = Lb1[f];
    for (int c = 0; c < 194; ++c) a += pooled[c] * LW1[c*64+f];
    float h = silu_f(a);
    hbuf[f] = h;
    __syncthreads();

    a = Lb2[f];
    for (int c = 0; c < 64; ++c) a += hbuf[c] * LW2[c*64+f];
    h = silu_f(a);
    __syncthreads();
    hbuf[f] = h;
    __syncthreads();

    if (f < 2) {
        a = Lb3[f];
        for (int c = 0; c < 64; ++c) a += hbuf[c] * LW3[c*2+f];
        out[g*2+f] = a;
    }
}

// ---------------------------------------------------------------------------
extern "C" void kernel_launch(void* const* d_in, const int* in_sizes, int n_in,
                              void* d_out, int out_size) {
    const float* x    = (const float*)d_in[0];
    const float* u    = (const float*)d_in[1];
    const int*   ei   = (const int*)d_in[2];
    const int*   batch= (const int*)d_in[3];
    const float* W1   = (const float*)d_in[4];
    const float* b1   = (const float*)d_in[5];
    const float* W2   = (const float*)d_in[6];
    const float* b2   = (const float*)d_in[7];
    const float* W3   = (const float*)d_in[8];
    const float* b3   = (const float*)d_in[9];
    const float* LW1  = (const float*)d_in[10];
    const float* Lb1  = (const float*)d_in[11];
    const float* LW2  = (const float*)d_in[12];
    const float* Lb2  = (const float*)d_in[13];
    const float* LW3  = (const float*)d_in[14];
    const float* Lb3  = (const float*)d_in[15];
    float* out = (float*)d_out;

    __half *Apre, *Bpre;
    float *x1, *x2;
    uint2* wimg;
    cudaGetSymbolAddress((void**)&Apre, g_Apre);
    cudaGetSymbolAddress((void**)&Bpre, g_Bpre);
    cudaGetSymbolAddress((void**)&x1,   g_x1);
    cudaGetSymbolAddress((void**)&x2,   g_x2);
    cudaGetSymbolAddress((void**)&wimg, g_wimg);

    cudaFuncSetAttribute(edge_kernel, cudaFuncAttributeMaxDynamicSharedMemorySize, EDGE_SMEM);

    const int* srcp = ei;
    const int* dstp = ei + EE;

    // zero both layer outputs up front (keeps edge_kernel at launch #6 for ncu)
    cudaMemsetAsync(x1, 0, (size_t)NN*FF*sizeof(float));
    cudaMemsetAsync(x2, 0, (size_t)NN*FF*sizeof(float));

    for (int l = 0; l < 2; ++l) {
        const float* xin = l ? (const float*)x1 : x;
        float* xout = l ? x2 : x1;
        precomp_kernel<<<dim3(3125, 3, 1), 256>>>(
            xin, W1 + (size_t)l*126*128, b1 + (size_t)l*128,
            W2 + (size_t)l*128*128, W3 + (size_t)l*128*64,
            Apre, Bpre, wimg);
        edge_kernel<<<EE/EPB, ETHREADS, EDGE_SMEM>>>(
            Apre, Bpre, xin, srcp, dstp,
            W1 + (size_t)l*126*128 + 125*128,
            wimg, b2 + (size_t)l*128,
            b3 + (size_t)l*64, xout);
    }
    pool_head_kernel<<<GG, 64>>>(x2, batch, u, LW1, Lb1, LW2, Lb2, LW3, Lb3, out);
}

// round 16
// speedup vs baseline: 1.9831x; 1.0328x over previous
#include <cuda_runtime.h>
#include <cuda_fp16.h>
#include <math.h>
#include <stdint.h>

#define NN 100000
#define EE 1600000
#define FF 64
#define HH 128
#define GG 256
#define EPB 128
#define ETHREADS 256

// smem layout (32-bit words): h1 tile, h2 tile, biases
#define SMW_H1 0          // [128][64] half2 words (h1; later fp32 m staging)
#define SMW_H2 8192       // [128][64] half2 words (h2)
#define SMW_B2 16384      // 128 floats
#define SMW_B3 16512      // 64 floats
#define EDGE_SMEM (16576 * 4)   // 66304 B -> 3 CTAs/SM (199 KB)

// scratch (static __device__ arrays: the sanctioned no-alloc workaround)
__device__ __half g_Apre[(size_t)NN*HH];   // fp16 precomputed node terms
__device__ __half g_Bpre[(size_t)NN*HH];
__device__ float g_x1[(size_t)NN*FF];
__device__ float g_x2[(size_t)NN*FF];
// fp16 warp-coalesced weight image (uint2 entries):
//   wq2 [0..4096):  idx = ((tile*8 + nf)*8 + ks)*32 + g*4 + tig
//                   n = tile*64 + nf*8 + g, k = ks*16 + tig*2
//                   entry = halves (W2[k][n], W2[k+1][n], W2[k+8][n], W2[k+9][n])
//   wq3 [4096..6144): idx2 = ((tile*4 + nf)*8 + ks)*32 + g*4 + tig, n = tile*32 + nf*8 + g
__device__ uint2 g_wimg[6144];

__device__ __forceinline__ float silu_f(float v) {
    return __fdividef(v, 1.0f + __expf(-v));
}
// 1-MUFU silu via tanh.approx (err ~2^-10.7, at the level of fp16 rounding of consumers)
__device__ __forceinline__ float silu_t(float v) {
    float t;
    asm("tanh.approx.f32 %0, %1;" : "=f"(t) : "f"(0.5f * v));
    return 0.5f * v * (1.0f + t);
}
__device__ __forceinline__ unsigned pk_h2(float a, float b) {
    __half2 h = __floats2half2_rn(a, b);
    return *reinterpret_cast<unsigned*>(&h);
}
__device__ __forceinline__ float2 uph2(unsigned u) {
    __half2 h = *reinterpret_cast<__half2*>(&u);
    return __half22float2(h);
}
// m16n8k16 fp16 MMA, fp32 accumulate
__device__ __forceinline__ void mma16(float* d, const unsigned* a, unsigned b0, unsigned b1) {
    asm volatile("mma.sync.aligned.m16n8k16.row.col.f32.f16.f16.f32 "
        "{%0,%1,%2,%3}, {%4,%5,%6,%7}, {%8,%9}, {%0,%1,%2,%3};"
        : "+f"(d[0]), "+f"(d[1]), "+f"(d[2]), "+f"(d[3])
        : "r"(a[0]), "r"(a[1]), "r"(a[2]), "r"(a[3]), "r"(b0), "r"(b1));
}
// packed f32x2 helpers (for precomp)
__device__ __forceinline__ void fma2(unsigned long long& d, unsigned long long a, unsigned long long b) {
    asm("fma.rn.f32x2 %0, %1, %2, %0;" : "+l"(d) : "l"(a), "l"(b));
}
__device__ __forceinline__ unsigned long long bcast2(float a) {
    unsigned long long r; asm("mov.b64 %0, {%1, %1};" : "=l"(r) : "f"(a)); return r;
}
__device__ __forceinline__ float2 unpk(unsigned long long v) {
    float2 r; asm("mov.b64 {%0, %1}, %2;" : "=f"(r.x), "=f"(r.y) : "l"(v)); return r;
}

// ---------------------------------------------------------------------------
// Combined precompute:
//   part 0: Apre = fp16(x @ W1[0:64] + b1)
//   part 1: Bpre = fp16(x[:,3:] @ W1[64:125])
//   part 2: warp-coalesced fp16 weight image (wq2, wq3)
// ---------------------------------------------------------------------------
__global__ void __launch_bounds__(256) precomp_kernel(
    const float* __restrict__ xin, const float* __restrict__ W1l, const float* __restrict__ b1l,
    const float* __restrict__ W2l, const float* __restrict__ W3l,
    __half* __restrict__ Apre, __half* __restrict__ Bpre, uint2* __restrict__ wimg)
{
    int part = blockIdx.y;
    int tid = threadIdx.x;

    if (part == 2) {
        int idx = blockIdx.x * 256 + tid;
        if (idx < 4096) {
            int rem = idx & 2047;
            int tile = idx >> 11;
            int nf = rem >> 8, ks = (rem >> 5) & 7, gg = (rem >> 2) & 7, tg = rem & 3;
            int n = tile*64 + nf*8 + gg;
            int k = ks*16 + tg*2;
            uint2 v;
            v.x = pk_h2(W2l[k*128 + n],     W2l[(k+1)*128 + n]);
            v.y = pk_h2(W2l[(k+8)*128 + n], W2l[(k+9)*128 + n]);
            wimg[idx] = v;
        } else if (idx < 6144) {
            int i2 = idx - 4096;
            int rem = i2 & 1023;
            int tile = i2 >> 10;
            int nf = rem >> 8, ks = (rem >> 5) & 7, gg = (rem >> 2) & 7, tg = rem & 3;
            int n = tile*32 + nf*8 + gg;
            int k = ks*16 + tg*2;
            uint2 v;
            v.x = pk_h2(W3l[k*64 + n],     W3l[(k+1)*64 + n]);
            v.y = pk_h2(W3l[(k+8)*64 + n], W3l[(k+9)*64 + n]);
            wimg[4096 + i2] = v;
        }
        return;
    }

    __shared__ float xs[32*64];
    size_t nb = (size_t)blockIdx.x * 32;

    const float4* xg = (const float4*)(xin + nb*64);
    float4* xs4 = (float4*)xs;
#pragma unroll
    for (int i = 0; i < 2; ++i) xs4[tid + i*256] = xg[tid + i*256];
    __syncthreads();

    int tx = tid & 31, ty = tid >> 5;
    unsigned long long acc[4][2];
#pragma unroll
    for (int a = 0; a < 4; ++a) { acc[a][0] = 0ull; acc[a][1] = 0ull; }

    int cbeg = part ? 3 : 0;
    const float* Wb = part ? (W1l + 61*128) : W1l;
#pragma unroll 4
    for (int c = cbeg; c < 64; ++c) {
        ulonglong2 wv = *(const ulonglong2*)(Wb + c*128 + tx*4);
#pragma unroll
        for (int ni = 0; ni < 4; ++ni) {
            unsigned long long av = bcast2(xs[(ty*4+ni)*64 + c]);
            fma2(acc[ni][0], av, wv.x);
            fma2(acc[ni][1], av, wv.y);
        }
    }

    float4 bv = make_float4(0.f,0.f,0.f,0.f);
    __half* outp;
    if (part) outp = Bpre;
    else { outp = Apre; bv = *(const float4*)(b1l + tx*4); }
    uint2* outu = (uint2*)outp;
#pragma unroll
    for (int ni = 0; ni < 4; ++ni) {
        float2 p0 = unpk(acc[ni][0]), p1 = unpk(acc[ni][1]);
        uint2 r;
        r.x = pk_h2(p0.x+bv.x, p0.y+bv.y);
        r.y = pk_h2(p1.x+bv.z, p1.y+bv.w);
        outu[(nb + ty*4 + ni)*32 + tx] = r;
    }
}

// ---------------------------------------------------------------------------
// Fused edge kernel, fp16 MMA m16n8k16, 3 CTAs/SM:
// gather h1 -> GEMM2 in two n-half passes (32 acc regs live) writing h2 into
// hs2 -> GEMM3 from hs2 -> fp32 m staged into hs1 -> coalesced atomic scatter.
// ---------------------------------------------------------------------------
__global__ void __launch_bounds__(ETHREADS, 3) edge_kernel(
    const __half* __restrict__ Apre, const __half* __restrict__ Bpre, const float* __restrict__ xin,
    const int* __restrict__ srcp, const int* __restrict__ dstp,
    const float* __restrict__ wdrow, const uint2* __restrict__ wimg, const float* __restrict__ b2l,
    const float* __restrict__ b3l, float* __restrict__ xout)
{
    extern __shared__ unsigned smw[];
    unsigned* hs1 = smw + SMW_H1;                // [128][64] half2 words (h1)
    unsigned* hs2 = smw + SMW_H2;                // [128][64] half2 words (h2)
    float* b2s = (float*)(smw + SMW_B2);
    float* b3s = (float*)(smw + SMW_B3);

    const int tid = threadIdx.x;
    const int w = tid >> 5, lane = tid & 31;
    const int g = lane >> 2, tig = lane & 3;
    const int eb = blockIdx.x * EPB;

    // stage biases (tiny)
    if (tid < 128) b2s[tid] = b2l[tid];
    else if (tid < 192) b3s[tid-128] = b3l[tid-128];

    // gather h1: warp covers 16 edges, lane covers k-chunk lane*4..lane*4+3
    {
        float4 wd4 = __ldg((const float4*)(wdrow + lane*4));
        int ids = (lane < 16) ? __ldg(srcp + eb + w*16 + lane)
                              : __ldg(dstp + eb + w*16 + (lane - 16));
        const uint2* Au = (const uint2*)Apre;
        const uint2* Bu = (const uint2*)Bpre;
#pragma unroll 4
        for (int it = 0; it < 16; ++it) {
            int s = __shfl_sync(0xffffffffu, ids, it);
            int d = __shfl_sync(0xffffffffu, ids, 16 + it);
            float4 xs4 = __ldg((const float4*)(xin + (size_t)s*64));
            float4 xd4 = __ldg((const float4*)(xin + (size_t)d*64));
            float dx = xs4.x - xd4.x, dy = xs4.y - xd4.y, dz = xs4.z - xd4.z;
            float dist2 = dx*dx + dy*dy + dz*dz;
            uint2 au = __ldg(Au + (size_t)d*32 + lane);
            uint2 bu = __ldg(Bu + (size_t)s*32 + lane);
            float2 a01 = uph2(au.x), a23 = uph2(au.y);
            float2 b01 = uph2(bu.x), b23 = uph2(bu.y);
            uint2 v;
            v.x = pk_h2(silu_t(a01.x + b01.x + dist2*wd4.x),
                        silu_t(a01.y + b01.y + dist2*wd4.y));
            v.y = pk_h2(silu_t(a23.x + b23.x + dist2*wd4.z),
                        silu_t(a23.y + b23.y + dist2*wd4.w));
            int e = w*16 + it;
            int kw = (lane*2) ^ ((e & 7) << 2);     // mask bits >=2: pair stays adjacent+aligned
            *(uint2*)(hs1 + e*64 + kw) = v;
        }
    }
    __syncthreads();

    const int e0 = (w & 3) * 32;
    const int n0 = (w >> 2) * 64;
    const int xm = g << 2;
    const unsigned* hA0 = hs1 + (e0 + g) * 64;
    const unsigned* hA1 = hs1 + (e0 + g + 8) * 64;
    const unsigned* hA2 = hs1 + (e0 + g + 16) * 64;
    const unsigned* hA3 = hs1 + (e0 + g + 24) * 64;
    const uint2* w2b = wimg + (w >> 2) * 2048 + lane;          // coalesced tile base
    const uint2* w3b = wimg + 4096 + (w >> 2) * 1024 + lane;

    // ---- GEMM2: [128e x 128] = h1 @ W2, two n-half passes (32 acc regs live) ----
#pragma unroll
    for (int p = 0; p < 2; ++p) {
        float acc[2][4][4];
#pragma unroll
        for (int mf = 0; mf < 2; ++mf)
#pragma unroll
            for (int nf = 0; nf < 4; ++nf)
#pragma unroll
                for (int q = 0; q < 4; ++q) acc[mf][nf][q] = 0.f;

#pragma unroll
        for (int ks = 0; ks < 8; ++ks) {
            int off1 = (ks*8 + tig) ^ xm;
            int off2 = (ks*8 + tig + 4) ^ xm;
            unsigned a[2][4];
            a[0][0] = hA0[off1]; a[0][1] = hA1[off1];
            a[0][2] = hA0[off2]; a[0][3] = hA1[off2];
            a[1][0] = hA2[off1]; a[1][1] = hA3[off1];
            a[1][2] = hA2[off2]; a[1][3] = hA3[off2];
#pragma unroll
            for (int nf = 0; nf < 4; ++nf) {
                uint2 wv = __ldg(w2b + (p*4 + nf)*256 + ks*32);
                mma16(acc[0][nf], a[0], wv.x, wv.y);
                mma16(acc[1][nf], a[1], wv.x, wv.y);
            }
        }

        // epilogue1 (this half): h2 = fp16(silu(D2 + b2)) into hs2
#pragma unroll
        for (int mf = 0; mf < 2; ++mf) {
            int elo = e0 + mf*16 + g;
            unsigned* hlo = hs2 + elo*64;
            unsigned* hhi = hs2 + (elo + 8)*64;
#pragma unroll
            for (int nf = 0; nf < 4; ++nf) {
                int n = n0 + (p*4 + nf)*8 + 2*tig;
                float bb0 = b2s[n], bb1 = b2s[n+1];
                int kwp = (n >> 1) ^ xm;
                hlo[kwp] = pk_h2(silu_t(acc[mf][nf][0] + bb0), silu_t(acc[mf][nf][1] + bb1));
                hhi[kwp] = pk_h2(silu_t(acc[mf][nf][2] + bb0), silu_t(acc[mf][nf][3] + bb1));
            }
        }
    }
    __syncthreads();   // all h2 writes complete

    // ---- GEMM3: [128e x 64] = h2 @ W3 (A-fragments from hs2) ----
    const int n03 = (w >> 2) * 32;
    const unsigned* hB0 = hs2 + (e0 + g) * 64;
    const unsigned* hB1 = hs2 + (e0 + g + 8) * 64;
    const unsigned* hB2 = hs2 + (e0 + g + 16) * 64;
    const unsigned* hB3 = hs2 + (e0 + g + 24) * 64;
    float acc3[2][4][4];
#pragma unroll
    for (int mf = 0; mf < 2; ++mf)
#pragma unroll
        for (int nf = 0; nf < 4; ++nf)
#pragma unroll
            for (int q = 0; q < 4; ++q) acc3[mf][nf][q] = 0.f;

#pragma unroll
    for (int ks = 0; ks < 8; ++ks) {
        int off1 = (ks*8 + tig) ^ xm;
        int off2 = (ks*8 + tig + 4) ^ xm;
        unsigned a[2][4];
        a[0][0] = hB0[off1]; a[0][1] = hB1[off1];
        a[0][2] = hB0[off2]; a[0][3] = hB1[off2];
        a[1][0] = hB2[off1]; a[1][1] = hB3[off1];
        a[1][2] = hB2[off2]; a[1][3] = hB3[off2];
#pragma unroll
        for (int nf = 0; nf < 4; ++nf) {
            uint2 wv = __ldg(w3b + nf*256 + ks*32);
            mma16(acc3[0][nf], a[0], wv.x, wv.y);
            mma16(acc3[1][nf], a[1], wv.x, wv.y);
        }
    }

    // ---- epilogue2a: stage m = silu(D3 + b3) as fp32 into hs1, col-swizzled ----
    // (hs1 is dead: all GEMM2 reads finished before the preceding __syncthreads)
    {
        float* ms = (float*)hs1;
#pragma unroll
        for (int mf = 0; mf < 2; ++mf) {
            int r1 = e0 + mf*16 + g;           // r1 & 7 == g
            int r2 = r1 + 8;
#pragma unroll
            for (int nf = 0; nf < 4; ++nf) {
                int c0 = n03 + nf*8 + 2*tig;
                float bb0 = b3s[c0], bb1 = b3s[c0+1];
                float2 v1 = make_float2(silu_f(acc3[mf][nf][0] + bb0),
                                        silu_f(acc3[mf][nf][1] + bb1));
                float2 v2 = make_float2(silu_f(acc3[mf][nf][2] + bb0),
                                        silu_f(acc3[mf][nf][3] + bb1));
                int sc = c0 ^ (g << 3);
                *(float2*)(ms + r1*64 + sc) = v1;
                *(float2*)(ms + r2*64 + sc) = v2;
            }
        }
    }
    __syncthreads();

    // ---- epilogue2b: coalesced scatter — per edge, 2 REDs of 32 consecutive lanes ----
    {
        const float* ms = (const float*)hs1;
        int dstid = __ldg(dstp + eb + w*16 + (lane & 15));
#pragma unroll 4
        for (int it = 0; it < 16; ++it) {
            int e = w*16 + it;
            int d = __shfl_sync(0xffffffffu, dstid, it);
            int msk = (e & 7) << 3;
            float v0 = ms[e*64 + (lane ^ msk)];
            float v1 = ms[e*64 + ((lane + 32) ^ msk)];
            float* op = xout + (size_t)d*64;
            atomicAdd(op + lane, v0);
            atomicAdd(op + lane + 32, v1);
        }
    }
}

// ---------------------------------------------------------------------------
// Pooling + readout MLP (unchanged)
// ---------------------------------------------------------------------------
__global__ void __launch_bounds__(64) pool_head_kernel(
    const float* __restrict__ xf, const int* __restrict__ batch, const float* __restrict__ u,
    const float* __restrict__ LW1, const float* __restrict__ Lb1,
    const float* __restrict__ LW2, const float* __restrict__ Lb2,
    const float* __restrict__ LW3, const float* __restrict__ Lb3,
    float* __restrict__ out)
{
    __shared__ float pooled[194];
    __shared__ float hbuf[64];
    int g = blockIdx.x, f = threadIdx.x;

    int start, end;
    {
        int lo = 0, hi = NN;
        while (lo < hi) { int m = (lo+hi) >> 1; if (batch[m] < g) lo = m+1; else hi = m; }
        start = lo;
        hi = NN;
        while (lo < hi) { int m = (lo+hi) >> 1; if (batch[m] < g+1) lo = m+1; else hi = m; }
        end = lo;
    }

    float s = 0.f, mx = -3.402823466e38f;
    for (int n = start; n < end; ++n) {
        float v = xf[(size_t)n*64 + f];
        s += v; mx = fmaxf(mx, v);
    }
    float cnt = fmaxf((float)(end - start), 1.f);
    pooled[f]      = s;
    pooled[64+f]   = s / cnt;
    pooled[128+f]  = mx;
    if (f < 2) pooled[192+f] = u[g*2+f];
    __syncthreads();

    float a = Lb1[f];
    for (int c = 0; c < 194; ++c) a += pooled[c] * LW1[c*64+f];
    float h = silu_f(a);
    hbuf[f] = h;
    __syncthreads();

    a = Lb2[f];
    for (int c = 0; c < 64; ++c) a += hbuf[c] * LW2[c*64+f];
    h = silu_f(a);
    __syncthreads();
    hbuf[f] = h;
    __syncthreads();

    if (f < 2) {
        a = Lb3[f];
        for (int c = 0; c < 64; ++c) a += hbuf[c] * LW3[c*2+f];
        out[g*2+f] = a;
    }
}

// ---------------------------------------------------------------------------
extern "C" void kernel_launch(void* const* d_in, const int* in_sizes, int n_in,
                              void* d_out, int out_size) {
    const float* x    = (const float*)d_in[0];
    const float* u    = (const float*)d_in[1];
    const int*   ei   = (const int*)d_in[2];
    const int*   batch= (const int*)d_in[3];
    const float* W1   = (const float*)d_in[4];
    const float* b1   = (const float*)d_in[5];
    const float* W2   = (const float*)d_in[6];
    const float* b2   = (const float*)d_in[7];
    const float* W3   = (const float*)d_in[8];
    const float* b3   = (const float*)d_in[9];
    const float* LW1  = (const float*)d_in[10];
    const float* Lb1  = (const float*)d_in[11];
    const float* LW2  = (const float*)d_in[12];
    const float* Lb2  = (const float*)d_in[13];
    const float* LW3  = (const float*)d_in[14];
    const float* Lb3  = (const float*)d_in[15];
    float* out = (float*)d_out;

    __half *Apre, *Bpre;
    float *x1, *x2;
    uint2* wimg;
    cudaGetSymbolAddress((void**)&Apre, g_Apre);
    cudaGetSymbolAddress((void**)&Bpre, g_Bpre);
    cudaGetSymbolAddress((void**)&x1,   g_x1);
    cudaGetSymbolAddress((void**)&x2,   g_x2);
    cudaGetSymbolAddress((void**)&wimg, g_wimg);

    cudaFuncSetAttribute(edge_kernel, cudaFuncAttributeMaxDynamicSharedMemorySize, EDGE_SMEM);

    const int* srcp = ei;
    const int* dstp = ei + EE;

    // zero both layer outputs up front (keeps edge_kernel at launch #6 for ncu)
    cudaMemsetAsync(x1, 0, (size_t)NN*FF*sizeof(float));
    cudaMemsetAsync(x2, 0, (size_t)NN*FF*sizeof(float));

    for (int l = 0; l < 2; ++l) {
        const float* xin = l ? (const float*)x1 : x;
        float* xout = l ? x2 : x1;
        precomp_kernel<<<dim3(3125, 3, 1), 256>>>(
            xin, W1 + (size_t)l*126*128, b1 + (size_t)l*128,
            W2 + (size_t)l*128*128, W3 + (size_t)l*128*64,
            Apre, Bpre, wimg);
        edge_kernel<<<EE/EPB, ETHREADS, EDGE_SMEM>>>(
            Apre, Bpre, xin, srcp, dstp,
            W1 + (size_t)l*126*128 + 125*128,
            wimg, b2 + (size_t)l*128,
            b3 + (size_t)l*64, xout);
    }
    pool_head_kernel<<<GG, 64>>>(x2, batch, u, LW1, Lb1, LW2, Lb2, LW3, Lb3, out);
}